// round 1
// baseline (speedup 1.0000x reference)
#include <cuda_runtime.h>
#include <math.h>

#define E 8
#define TOPK 2
#define CAP 512
#define H 2048
#define F 8192
#define NSLOT (E*CAP)   // 4096

// ---------------- scratch (no allocation allowed) ----------------
__device__ float g_buf[(size_t)NSLOT * H];   // 32 MB dispatch buffer
__device__ float g_act[(size_t)NSLOT * F];   // 128 MB gelu activations
__device__ float g_h  [(size_t)NSLOT * H];   // 32 MB expert output
__device__ int   g_entry_expert[2 * 2048];   // [K*N] slot-major
__device__ float g_entry_prob  [2 * 2048];
__device__ int   g_entry_dest  [2 * 2048];   // dest slot or -1 (dropped)
__device__ int   g_slot_token  [NSLOT];      // token feeding each slot, or -1

// ---------------- router: logits -> softmax -> top2 ----------------
__global__ void router_kernel(const float* __restrict__ x,
                              const float* __restrict__ rw,
                              int N) {
    const int t = blockIdx.x;
    const int tid = threadIdx.x;            // 256 threads, 8 warps
    const int lane = tid & 31, warp = tid >> 5;

    __shared__ float xs[H];
    const float4* xv = (const float4*)(x + (size_t)t * H);
    float4* xsv = (float4*)xs;
    for (int i = tid; i < H / 4; i += 256) xsv[i] = xv[i];
    __syncthreads();

    // warp w computes logit for expert w
    const float* wr = rw + (size_t)warp * H;
    float s = 0.f;
    for (int i = lane; i < H; i += 32) s += xs[i] * wr[i];
    #pragma unroll
    for (int o = 16; o; o >>= 1) s += __shfl_xor_sync(0xffffffffu, s, o);

    __shared__ float logits[E];
    if (lane == 0) logits[warp] = s;
    __syncthreads();

    if (tid == 0) {
        float m = logits[0];
        #pragma unroll
        for (int e = 1; e < E; e++) m = fmaxf(m, logits[e]);
        float p[E], den = 0.f;
        #pragma unroll
        for (int e = 0; e < E; e++) { p[e] = __expf(logits[e] - m); den += p[e]; }
        float inv = 1.f / den;
        #pragma unroll
        for (int e = 0; e < E; e++) p[e] *= inv;
        // top-2, ties -> lower index (strict > keeps first occurrence)
        int i0 = 0;
        #pragma unroll
        for (int e = 1; e < E; e++) if (p[e] > p[i0]) i0 = e;
        int i1 = (i0 == 0) ? 1 : 0;
        #pragma unroll
        for (int e = 0; e < E; e++) if (e != i0 && p[e] > p[i1]) i1 = e;
        g_entry_expert[t]     = i0; g_entry_prob[t]     = p[i0];
        g_entry_expert[N + t] = i1; g_entry_prob[N + t] = p[i1];
    }
}

// ---------------- per-expert sequential position scan ----------------
__global__ void assign_kernel(int N) {
    const int NK = TOPK * N;
    __shared__ int se[2 * 2048];
    for (int i = threadIdx.x; i < NSLOT; i += blockDim.x) g_slot_token[i] = -1;
    for (int i = threadIdx.x; i < NK; i += blockDim.x) se[i] = g_entry_expert[i];
    __syncthreads();
    if (threadIdx.x < E) {
        const int e = threadIdx.x;
        int cnt = 0;
        for (int i = 0; i < NK; i++) {
            if (se[i] == e) {
                if (cnt < CAP) {
                    int d = e * CAP + cnt;
                    g_entry_dest[i] = d;
                    g_slot_token[d] = i % N;   // token index
                } else {
                    g_entry_dest[i] = -1;      // dropped at capacity
                }
                cnt++;
            }
        }
    }
}

// ---------------- gather tokens into dispatch buffer ----------------
__global__ void dispatch_kernel(const float* __restrict__ x) {
    const int slot = blockIdx.x;
    const int t = g_slot_token[slot];
    float4* dst = (float4*)(g_buf + (size_t)slot * H);
    if (t >= 0) {
        const float4* src = (const float4*)(x + (size_t)t * H);
        for (int i = threadIdx.x; i < H / 4; i += blockDim.x) dst[i] = src[i];
    } else {
        const float4 z = make_float4(0.f, 0.f, 0.f, 0.f);
        for (int i = threadIdx.x; i < H / 4; i += blockDim.x) dst[i] = z;
    }
}

// ---------------- GEMM: C[m,n] = act(sum_k A[m,k]*B[n,k] + bias[n]) ----------------
// A row-major [M,K], B row-major [N,K] (both K-contiguous), 128x128x16 tile.
template<bool GELU>
__global__ __launch_bounds__(256, 2)
void gemm_nt_bias(const float* __restrict__ A, const float* __restrict__ B,
                  const float* __restrict__ bias, float* __restrict__ C,
                  int M, int N, int K) {
    const int BM = 128, BN = 128, BK = 16;
    __shared__ float As[BK][BM];
    __shared__ float Bs[BK][BN];

    const int bm = blockIdx.y * BM;
    const int bn = blockIdx.x * BN;
    const int tid = threadIdx.x;       // 0..255
    const int tx = tid & 15;           // 16 cols of threads
    const int ty = tid >> 4;           // 16 rows of threads

    float acc[8][8];
    #pragma unroll
    for (int i = 0; i < 8; i++)
        #pragma unroll
        for (int j = 0; j < 8; j++) acc[i][j] = 0.f;

    for (int k0 = 0; k0 < K; k0 += BK) {
        // load 128x16 tile of A (512 float4, 2 per thread)
        #pragma unroll
        for (int l = 0; l < 2; l++) {
            int idx = tid + l * 256;     // 0..511
            int row = idx >> 2;          // 0..127
            int k4  = idx & 3;           // 0..3
            float4 v = *(const float4*)&A[(size_t)(bm + row) * K + k0 + k4 * 4];
            As[k4 * 4 + 0][row] = v.x; As[k4 * 4 + 1][row] = v.y;
            As[k4 * 4 + 2][row] = v.z; As[k4 * 4 + 3][row] = v.w;
        }
        #pragma unroll
        for (int l = 0; l < 2; l++) {
            int idx = tid + l * 256;
            int row = idx >> 2;
            int k4  = idx & 3;
            float4 v = *(const float4*)&B[(size_t)(bn + row) * K + k0 + k4 * 4];
            Bs[k4 * 4 + 0][row] = v.x; Bs[k4 * 4 + 1][row] = v.y;
            Bs[k4 * 4 + 2][row] = v.z; Bs[k4 * 4 + 3][row] = v.w;
        }
        __syncthreads();

        #pragma unroll
        for (int k = 0; k < BK; k++) {
            float4 a0 = *(const float4*)&As[k][ty * 8];
            float4 a1 = *(const float4*)&As[k][ty * 8 + 4];
            float4 b0 = *(const float4*)&Bs[k][tx * 8];
            float4 b1 = *(const float4*)&Bs[k][tx * 8 + 4];
            float a[8] = {a0.x,a0.y,a0.z,a0.w,a1.x,a1.y,a1.z,a1.w};
            float b[8] = {b0.x,b0.y,b0.z,b0.w,b1.x,b1.y,b1.z,b1.w};
            #pragma unroll
            for (int i = 0; i < 8; i++)
                #pragma unroll
                for (int j = 0; j < 8; j++)
                    acc[i][j] = fmaf(a[i], b[j], acc[i][j]);
        }
        __syncthreads();
    }

    // epilogue
    #pragma unroll
    for (int i = 0; i < 8; i++) {
        int row = bm + ty * 8 + i;
        #pragma unroll
        for (int j = 0; j < 8; j += 4) {
            int col = bn + tx * 8 + j;
            float4 v;
            v.x = acc[i][j+0] + bias[col+0];
            v.y = acc[i][j+1] + bias[col+1];
            v.z = acc[i][j+2] + bias[col+2];
            v.w = acc[i][j+3] + bias[col+3];
            if (GELU) {
                v.x = 0.5f * v.x * (1.f + erff(v.x * 0.7071067811865475f));
                v.y = 0.5f * v.y * (1.f + erff(v.y * 0.7071067811865475f));
                v.z = 0.5f * v.z * (1.f + erff(v.z * 0.7071067811865475f));
                v.w = 0.5f * v.w * (1.f + erff(v.w * 0.7071067811865475f));
            }
            *(float4*)&C[(size_t)row * N + col] = v;
        }
    }
}

// ---------------- weighted combine back to tokens ----------------
__global__ void combine_kernel(int N, float* __restrict__ out) {
    const int t = blockIdx.x;
    const int d0 = g_entry_dest[t];
    const int d1 = g_entry_dest[N + t];
    const float p0 = g_entry_prob[t];
    const float p1 = g_entry_prob[N + t];
    const float4* h0 = (d0 >= 0) ? (const float4*)(g_h + (size_t)d0 * H) : nullptr;
    const float4* h1 = (d1 >= 0) ? (const float4*)(g_h + (size_t)d1 * H) : nullptr;
    float4* o = (float4*)(out + (size_t)t * H);
    for (int i = threadIdx.x; i < H / 4; i += blockDim.x) {
        float4 acc = make_float4(0.f, 0.f, 0.f, 0.f);
        if (h0) { float4 v = h0[i]; acc.x += p0*v.x; acc.y += p0*v.y; acc.z += p0*v.z; acc.w += p0*v.w; }
        if (h1) { float4 v = h1[i]; acc.x += p1*v.x; acc.y += p1*v.y; acc.z += p1*v.z; acc.w += p1*v.w; }
        o[i] = acc;
    }
}

// ---------------- launch ----------------
extern "C" void kernel_launch(void* const* d_in, const int* in_sizes, int n_in,
                              void* d_out, int out_size) {
    const float* x   = (const float*)d_in[0];  // [N, H]
    const float* rw  = (const float*)d_in[1];  // [E, H]
    const float* w1  = (const float*)d_in[2];  // [F, H]
    const float* b1  = (const float*)d_in[3];  // [F]
    const float* w2  = (const float*)d_in[4];  // [H, F]
    const float* b2  = (const float*)d_in[5];  // [H]
    float* out = (float*)d_out;

    const int N = in_sizes[0] / H;             // 2048 tokens

    float* buf; cudaGetSymbolAddress((void**)&buf, g_buf);
    float* act; cudaGetSymbolAddress((void**)&act, g_act);
    float* hbf; cudaGetSymbolAddress((void**)&hbf, g_h);

    router_kernel<<<N, 256>>>(x, rw, N);
    assign_kernel<<<1, 256>>>(N);
    dispatch_kernel<<<NSLOT, 256>>>(x);

    {   // GEMM1: buf[4096,2048] @ w1^T -> gelu -> act[4096,8192]
        dim3 grid(F / 128, NSLOT / 128);
        gemm_nt_bias<true><<<grid, 256>>>(buf, w1, b1, act, NSLOT, F, H);
    }
    {   // GEMM2: act[4096,8192] @ w2^T + b2 -> h[4096,2048]
        dim3 grid(H / 128, NSLOT / 128);
        gemm_nt_bias<false><<<grid, 256>>>(act, w2, b2, hbf, NSLOT, H, F);
    }

    combine_kernel<<<N, 256>>>(N, out);
}

// round 3
// speedup vs baseline: 2.9767x; 2.9767x over previous
#include <cuda_runtime.h>
#include <cstdint>
#include <math.h>

#define E 8
#define TOPK 2
#define CAP 512
#define H 2048
#define F 8192
#define NSLOT (E*CAP)   // 4096

// ---------------- scratch (no allocation allowed) ----------------
__device__ float g_buf[(size_t)NSLOT * H];   // 32 MB dispatch buffer
__device__ float g_act[(size_t)NSLOT * F];   // 128 MB gelu activations
__device__ float g_h  [(size_t)NSLOT * H];   // 32 MB expert output
__device__ int   g_entry_expert[2 * 2048];
__device__ float g_entry_prob  [2 * 2048];
__device__ int   g_entry_dest  [2 * 2048];
__device__ int   g_slot_token  [NSLOT];

// ---------------- helpers ----------------
__device__ __forceinline__ uint32_t smem_u32(const void* p) {
    uint32_t a;
    asm("{ .reg .u64 t; cvta.to.shared.u64 t, %1; cvt.u32.u64 %0, t; }"
        : "=r"(a) : "l"(p));
    return a;
}
__device__ __forceinline__ uint32_t tf32u(float x) {
    uint32_t u;
    asm("cvt.rna.tf32.f32 %0, %1;" : "=r"(u) : "f"(x));
    return u;
}
__device__ __forceinline__ void cp16(uint32_t dst, const void* src) {
    asm volatile("cp.async.cg.shared.global [%0], [%1], 16;"
                 :: "r"(dst), "l"(src) : "memory");
}
__device__ __forceinline__ void mma_tf32(float* c, const uint32_t* a, const uint32_t* b) {
    asm volatile(
        "mma.sync.aligned.m16n8k8.row.col.f32.tf32.tf32.f32 "
        "{%0,%1,%2,%3}, {%4,%5,%6,%7}, {%8,%9}, {%0,%1,%2,%3};"
        : "+f"(c[0]), "+f"(c[1]), "+f"(c[2]), "+f"(c[3])
        : "r"(a[0]), "r"(a[1]), "r"(a[2]), "r"(a[3]), "r"(b[0]), "r"(b[1]));
}

// ---------------- router ----------------
__global__ void router_kernel(const float* __restrict__ x,
                              const float* __restrict__ rw, int N) {
    const int t = blockIdx.x;
    const int tid = threadIdx.x;
    const int lane = tid & 31, warp = tid >> 5;

    __shared__ float xs[H];
    const float4* xv = (const float4*)(x + (size_t)t * H);
    float4* xsv = (float4*)xs;
    for (int i = tid; i < H / 4; i += 256) xsv[i] = xv[i];
    __syncthreads();

    const float* wr = rw + (size_t)warp * H;
    float s = 0.f;
    for (int i = lane; i < H; i += 32) s += xs[i] * wr[i];
    #pragma unroll
    for (int o = 16; o; o >>= 1) s += __shfl_xor_sync(0xffffffffu, s, o);

    __shared__ float logits[E];
    if (lane == 0) logits[warp] = s;
    __syncthreads();

    if (tid == 0) {
        float m = logits[0];
        #pragma unroll
        for (int e = 1; e < E; e++) m = fmaxf(m, logits[e]);
        float p[E], den = 0.f;
        #pragma unroll
        for (int e = 0; e < E; e++) { p[e] = __expf(logits[e] - m); den += p[e]; }
        float inv = 1.f / den;
        #pragma unroll
        for (int e = 0; e < E; e++) p[e] *= inv;
        int i0 = 0;
        #pragma unroll
        for (int e = 1; e < E; e++) if (p[e] > p[i0]) i0 = e;
        int i1 = (i0 == 0) ? 1 : 0;
        #pragma unroll
        for (int e = 0; e < E; e++) if (e != i0 && p[e] > p[i1]) i1 = e;
        g_entry_expert[t]     = i0; g_entry_prob[t]     = p[i0];
        g_entry_expert[N + t] = i1; g_entry_prob[N + t] = p[i1];
    }
}

// ---------------- per-expert sequential position scan ----------------
__global__ void assign_kernel(int N) {
    const int NK = TOPK * N;
    __shared__ int se[2 * 2048];
    for (int i = threadIdx.x; i < NSLOT; i += blockDim.x) g_slot_token[i] = -1;
    for (int i = threadIdx.x; i < NK; i += blockDim.x) se[i] = g_entry_expert[i];
    __syncthreads();
    if (threadIdx.x < E) {
        const int e = threadIdx.x;
        int cnt = 0;
        for (int i = 0; i < NK; i++) {
            if (se[i] == e) {
                if (cnt < CAP) {
                    int d = e * CAP + cnt;
                    g_entry_dest[i] = d;
                    g_slot_token[d] = i % N;
                } else {
                    g_entry_dest[i] = -1;
                }
                cnt++;
            }
        }
    }
}

// ---------------- gather tokens into dispatch buffer ----------------
__global__ void dispatch_kernel(const float* __restrict__ x) {
    const int slot = blockIdx.x;
    const int t = g_slot_token[slot];
    float4* dst = (float4*)(g_buf + (size_t)slot * H);
    if (t >= 0) {
        const float4* src = (const float4*)(x + (size_t)t * H);
        for (int i = threadIdx.x; i < H / 4; i += blockDim.x) dst[i] = src[i];
    } else {
        const float4 z = make_float4(0.f, 0.f, 0.f, 0.f);
        for (int i = threadIdx.x; i < H / 4; i += blockDim.x) dst[i] = z;
    }
}

// ---------------- TF32 mma.sync GEMM: C = act(A @ B^T + bias) ----------------
// A row-major [M,K], B row-major [N,K]. Block 128x128x32, 8 warps (2M x 4N),
// warp tile 64x32 (4x4 m16n8k8). 3-stage cp.async pipeline.
// Smem tiles stored [row][k] with XOR swizzle: float (r,k) at r*32 + (k ^ ((r&7)<<2)).
#define BM 128
#define BN 128
#define BK 32
#define STAGES 3
#define STAGE_FLOATS (2 * BM * BK)               // 8192 floats = 32KB
#define GEMM_SMEM (STAGES * STAGE_FLOATS * 4)    // 96KB

template<bool GELU>
__global__ __launch_bounds__(256, 2)
void gemm_mma(const float* __restrict__ A, const float* __restrict__ B,
              const float* __restrict__ bias, float* __restrict__ C,
              int Ncols, int K) {
    extern __shared__ float sm[];
    const uint32_t sbase = smem_u32(sm);
    const int tid = threadIdx.x, lane = tid & 31, wid = tid >> 5;
    const int wm = wid & 1, wn = wid >> 1;       // warp grid 2(M) x 4(N)
    const int bm = blockIdx.y * BM, bn = blockIdx.x * BN;
    const int lr = lane >> 2, lc = lane & 3;
    const int KT = K / BK;

    float acc[4][4][4];
    #pragma unroll
    for (int i = 0; i < 4; i++)
        #pragma unroll
        for (int j = 0; j < 4; j++)
            #pragma unroll
            for (int q = 0; q < 4; q++) acc[i][j][q] = 0.f;

    // loader: stage s gets K-slab t
    const int lrow = tid >> 3;        // 0..31 (row group base; 4 rows per warp pass)
    const int lj   = tid & 7;         // chunk in row
    auto load_stage = [&](int t, int s) {
        const int k0 = t * BK;
        const uint32_t stA = sbase + s * (STAGE_FLOATS * 4);
        const uint32_t stB = stA + BM * BK * 4;
        #pragma unroll
        for (int l = 0; l < 4; l++) {
            const int row = lrow + l * 32;
            const uint32_t doff = row * 128 + ((lj ^ (row & 7)) << 4);
            cp16(stA + doff, A + (size_t)(bm + row) * K + k0 + lj * 4);
            cp16(stB + doff, B + (size_t)(bn + row) * K + k0 + lj * 4);
        }
    };

    #pragma unroll
    for (int t = 0; t < STAGES - 1; t++) {
        load_stage(t, t);
        asm volatile("cp.async.commit_group;" ::: "memory");
    }

    for (int t = 0; t < KT; t++) {
        asm volatile("cp.async.wait_group %0;" :: "n"(STAGES - 2) : "memory");
        __syncthreads();

        const int tn = t + STAGES - 1;
        if (tn < KT) load_stage(tn, tn % STAGES);
        asm volatile("cp.async.commit_group;" ::: "memory");

        const float* sA = sm + (t % STAGES) * STAGE_FLOATS;
        const float* sB = sA + BM * BK;

        #pragma unroll
        for (int ks = 0; ks < 4; ks++) {
            uint32_t a[4][4], b[4][2];
            const int k = ks * 8 + lc;
            #pragma unroll
            for (int mt = 0; mt < 4; mt++) {
                const int m0 = wm * 64 + mt * 16 + lr;
                const int xm = (m0 & 7) << 2;
                a[mt][0] = tf32u(sA[m0 * 32 + (k ^ xm)]);
                a[mt][1] = tf32u(sA[(m0 + 8) * 32 + (k ^ xm)]);
                a[mt][2] = tf32u(sA[m0 * 32 + ((k + 4) ^ xm)]);
                a[mt][3] = tf32u(sA[(m0 + 8) * 32 + ((k + 4) ^ xm)]);
            }
            #pragma unroll
            for (int nt = 0; nt < 4; nt++) {
                const int n = wn * 32 + nt * 8 + lr;
                const int xn = (n & 7) << 2;
                b[nt][0] = tf32u(sB[n * 32 + (k ^ xn)]);
                b[nt][1] = tf32u(sB[n * 32 + ((k + 4) ^ xn)]);
            }
            #pragma unroll
            for (int mt = 0; mt < 4; mt++)
                #pragma unroll
                for (int nt = 0; nt < 4; nt++)
                    mma_tf32(acc[mt][nt], a[mt], b[nt]);
        }
    }

    // epilogue: bias (+GELU), fp32 out
    #pragma unroll
    for (int mt = 0; mt < 4; mt++) {
        const int row0 = bm + wm * 64 + mt * 16 + lr;
        #pragma unroll
        for (int nt = 0; nt < 4; nt++) {
            const int col = bn + wn * 32 + nt * 8 + 2 * lc;
            const float b0 = __ldg(&bias[col]), b1 = __ldg(&bias[col + 1]);
            float v0 = acc[mt][nt][0] + b0;
            float v1 = acc[mt][nt][1] + b1;
            float v2 = acc[mt][nt][2] + b0;
            float v3 = acc[mt][nt][3] + b1;
            if (GELU) {
                v0 = 0.5f * v0 * (1.f + erff(v0 * 0.7071067811865475f));
                v1 = 0.5f * v1 * (1.f + erff(v1 * 0.7071067811865475f));
                v2 = 0.5f * v2 * (1.f + erff(v2 * 0.7071067811865475f));
                v3 = 0.5f * v3 * (1.f + erff(v3 * 0.7071067811865475f));
            }
            *(float2*)&C[(size_t)row0 * Ncols + col]       = make_float2(v0, v1);
            *(float2*)&C[(size_t)(row0 + 8) * Ncols + col] = make_float2(v2, v3);
        }
    }
}

// ---------------- weighted combine ----------------
__global__ void combine_kernel(int N, float* __restrict__ out) {
    const int t = blockIdx.x;
    const int d0 = g_entry_dest[t];
    const int d1 = g_entry_dest[N + t];
    const float p0 = g_entry_prob[t];
    const float p1 = g_entry_prob[N + t];
    const float4* h0 = (d0 >= 0) ? (const float4*)(g_h + (size_t)d0 * H) : nullptr;
    const float4* h1 = (d1 >= 0) ? (const float4*)(g_h + (size_t)d1 * H) : nullptr;
    float4* o = (float4*)(out + (size_t)t * H);
    for (int i = threadIdx.x; i < H / 4; i += blockDim.x) {
        float4 acc = make_float4(0.f, 0.f, 0.f, 0.f);
        if (h0) { float4 v = h0[i]; acc.x += p0*v.x; acc.y += p0*v.y; acc.z += p0*v.z; acc.w += p0*v.w; }
        if (h1) { float4 v = h1[i]; acc.x += p1*v.x; acc.y += p1*v.y; acc.z += p1*v.z; acc.w += p1*v.w; }
        o[i] = acc;
    }
}

// ---------------- launch ----------------
extern "C" void kernel_launch(void* const* d_in, const int* in_sizes, int n_in,
                              void* d_out, int out_size) {
    const float* x  = (const float*)d_in[0];
    const float* rw = (const float*)d_in[1];
    const float* w1 = (const float*)d_in[2];
    const float* b1 = (const float*)d_in[3];
    const float* w2 = (const float*)d_in[4];
    const float* b2 = (const float*)d_in[5];
    float* out = (float*)d_out;

    const int N = in_sizes[0] / H;   // 2048

    float* buf; cudaGetSymbolAddress((void**)&buf, g_buf);
    float* act; cudaGetSymbolAddress((void**)&act, g_act);
    float* hbf; cudaGetSymbolAddress((void**)&hbf, g_h);

    cudaFuncSetAttribute(gemm_mma<true>,
                         cudaFuncAttributeMaxDynamicSharedMemorySize, GEMM_SMEM);
    cudaFuncSetAttribute(gemm_mma<false>,
                         cudaFuncAttributeMaxDynamicSharedMemorySize, GEMM_SMEM);

    router_kernel<<<N, 256>>>(x, rw, N);
    assign_kernel<<<1, 256>>>(N);
    dispatch_kernel<<<NSLOT, 256>>>(x);

    // GEMM1: buf[4096,2048] @ w1^T -> gelu -> act[4096,8192]
    gemm_mma<true><<<dim3(F / BN, NSLOT / BM), 256, GEMM_SMEM>>>(
        buf, w1, b1, act, F, H);
    // GEMM2: act[4096,8192] @ w2^T + b2 -> h[4096,2048]
    gemm_mma<false><<<dim3(H / BN, NSLOT / BM), 256, GEMM_SMEM>>>(
        act, w2, b2, hbf, H, F);

    combine_kernel<<<N, 256>>>(N, out);
}

// round 4
// speedup vs baseline: 3.5204x; 1.1827x over previous
#include <cuda_runtime.h>
#include <cstdint>
#include <math.h>

#define E 8
#define TOPK 2
#define CAP 512
#define H 2048
#define F 8192
#define NSLOT (E*CAP)   // 4096

// ---------------- scratch (no allocation allowed) ----------------
__device__ float g_buf[(size_t)NSLOT * H];   // dispatch buffer (tf32-rounded)
__device__ float g_act[(size_t)NSLOT * F];   // gelu acts (tf32-rounded)
__device__ float g_h  [(size_t)NSLOT * H];   // expert output fp32
__device__ float g_w1r[(size_t)F * H];       // w1 tf32-rounded
__device__ float g_w2r[(size_t)H * F];       // w2 tf32-rounded
__device__ int   g_entry_expert[2 * 2048];
__device__ float g_entry_prob  [2 * 2048];
__device__ int   g_entry_dest  [2 * 2048];
__device__ int   g_slot_token  [NSLOT];

// ---------------- helpers ----------------
__device__ __forceinline__ uint32_t smem_u32(const void* p) {
    uint32_t a;
    asm("{ .reg .u64 t; cvta.to.shared.u64 t, %1; cvt.u32.u64 %0, t; }"
        : "=r"(a) : "l"(p));
    return a;
}
__device__ __forceinline__ float tf32r(float x) {
    uint32_t u;
    asm("cvt.rna.tf32.f32 %0, %1;" : "=r"(u) : "f"(x));
    return __uint_as_float(u);
}
__device__ __forceinline__ void cp16(uint32_t dst, const void* src) {
    asm volatile("cp.async.cg.shared.global [%0], [%1], 16;"
                 :: "r"(dst), "l"(src) : "memory");
}
__device__ __forceinline__ void mma_tf32(float* c, const uint32_t* a, const uint32_t* b) {
    asm volatile(
        "mma.sync.aligned.m16n8k8.row.col.f32.tf32.tf32.f32 "
        "{%0,%1,%2,%3}, {%4,%5,%6,%7}, {%8,%9}, {%0,%1,%2,%3};"
        : "+f"(c[0]), "+f"(c[1]), "+f"(c[2]), "+f"(c[3])
        : "r"(a[0]), "r"(a[1]), "r"(a[2]), "r"(a[3]), "r"(b[0]), "r"(b[1]));
}

// ---------------- tf32 rounding pass (weights) ----------------
__global__ void round_tf32(const float* __restrict__ src, float* __restrict__ dst,
                           size_t n4) {
    size_t i = (size_t)blockIdx.x * blockDim.x + threadIdx.x;
    if (i < n4) {
        float4 v = ((const float4*)src)[i];
        ((float4*)dst)[i] = make_float4(tf32r(v.x), tf32r(v.y), tf32r(v.z), tf32r(v.w));
    }
}

// ---------------- router ----------------
__global__ void router_kernel(const float* __restrict__ x,
                              const float* __restrict__ rw, int N) {
    const int t = blockIdx.x;
    const int tid = threadIdx.x;
    const int lane = tid & 31, warp = tid >> 5;

    __shared__ float xs[H];
    const float4* xv = (const float4*)(x + (size_t)t * H);
    float4* xsv = (float4*)xs;
    for (int i = tid; i < H / 4; i += 256) xsv[i] = xv[i];
    __syncthreads();

    const float* wr = rw + (size_t)warp * H;
    float s = 0.f;
    for (int i = lane; i < H; i += 32) s += xs[i] * wr[i];
    #pragma unroll
    for (int o = 16; o; o >>= 1) s += __shfl_xor_sync(0xffffffffu, s, o);

    __shared__ float logits[E];
    if (lane == 0) logits[warp] = s;
    __syncthreads();

    if (tid == 0) {
        float m = logits[0];
        #pragma unroll
        for (int e = 1; e < E; e++) m = fmaxf(m, logits[e]);
        float p[E], den = 0.f;
        #pragma unroll
        for (int e = 0; e < E; e++) { p[e] = __expf(logits[e] - m); den += p[e]; }
        float inv = 1.f / den;
        #pragma unroll
        for (int e = 0; e < E; e++) p[e] *= inv;
        int i0 = 0;
        #pragma unroll
        for (int e = 1; e < E; e++) if (p[e] > p[i0]) i0 = e;
        int i1 = (i0 == 0) ? 1 : 0;
        #pragma unroll
        for (int e = 0; e < E; e++) if (e != i0 && p[e] > p[i1]) i1 = e;
        g_entry_expert[t]     = i0; g_entry_prob[t]     = p[i0];
        g_entry_expert[N + t] = i1; g_entry_prob[N + t] = p[i1];
    }
}

// ---------------- per-expert sequential position scan ----------------
__global__ void assign_kernel(int N) {
    const int NK = TOPK * N;
    __shared__ int se[2 * 2048];
    for (int i = threadIdx.x; i < NSLOT; i += blockDim.x) g_slot_token[i] = -1;
    for (int i = threadIdx.x; i < NK; i += blockDim.x) se[i] = g_entry_expert[i];
    __syncthreads();
    if (threadIdx.x < E) {
        const int e = threadIdx.x;
        int cnt = 0;
        for (int i = 0; i < NK; i++) {
            if (se[i] == e) {
                if (cnt < CAP) {
                    int d = e * CAP + cnt;
                    g_entry_dest[i] = d;
                    g_slot_token[d] = i % N;
                } else {
                    g_entry_dest[i] = -1;
                }
                cnt++;
            }
        }
    }
}

// ---------------- gather tokens (tf32-rounded) into dispatch buffer ----------------
__global__ void dispatch_kernel(const float* __restrict__ x) {
    const int slot = blockIdx.x;
    const int t = g_slot_token[slot];
    float4* dst = (float4*)(g_buf + (size_t)slot * H);
    if (t >= 0) {
        const float4* src = (const float4*)(x + (size_t)t * H);
        for (int i = threadIdx.x; i < H / 4; i += blockDim.x) {
            float4 v = src[i];
            dst[i] = make_float4(tf32r(v.x), tf32r(v.y), tf32r(v.z), tf32r(v.w));
        }
    } else {
        const float4 z = make_float4(0.f, 0.f, 0.f, 0.f);
        for (int i = threadIdx.x; i < H / 4; i += blockDim.x) dst[i] = z;
    }
}

// ---------------- TF32 mma.sync GEMM: C = act(A @ B^T + bias) ----------------
// Operands pre-rounded to tf32 in gmem -> no cvt in the hot loop.
// Block 128x128x32, 8 warps (2M x 4N), warp tile 64x32, 3-stage cp.async.
#define BM 128
#define BN 128
#define BK 32
#define STAGES 3
#define STAGE_FLOATS (2 * BM * BK)               // 32KB
#define GEMM_SMEM (STAGES * STAGE_FLOATS * 4)    // 96KB

template<bool GELU, bool ROUNDOUT>
__global__ __launch_bounds__(256, 2)
void gemm_mma(const float* __restrict__ A, const float* __restrict__ B,
              const float* __restrict__ bias, float* __restrict__ C,
              int Ncols, int K) {
    extern __shared__ float sm[];
    const uint32_t sbase = smem_u32(sm);
    const int tid = threadIdx.x, lane = tid & 31, wid = tid >> 5;
    const int wm = wid & 1, wn = wid >> 1;
    const int bm = blockIdx.y * BM, bn = blockIdx.x * BN;
    const int lr = lane >> 2, lc = lane & 3;
    const int KT = K / BK;

    float acc[4][4][4];
    #pragma unroll
    for (int i = 0; i < 4; i++)
        #pragma unroll
        for (int j = 0; j < 4; j++)
            #pragma unroll
            for (int q = 0; q < 4; q++) acc[i][j][q] = 0.f;

    const int lrow = tid >> 3;
    const int lj   = tid & 7;
    auto load_stage = [&](int t, int s) {
        const int k0 = t * BK;
        const uint32_t stA = sbase + s * (STAGE_FLOATS * 4);
        const uint32_t stB = stA + BM * BK * 4;
        #pragma unroll
        for (int l = 0; l < 4; l++) {
            const int row = lrow + l * 32;
            const uint32_t doff = row * 128 + ((lj ^ (row & 7)) << 4);
            cp16(stA + doff, A + (size_t)(bm + row) * K + k0 + lj * 4);
            cp16(stB + doff, B + (size_t)(bn + row) * K + k0 + lj * 4);
        }
    };

    #pragma unroll
    for (int t = 0; t < STAGES - 1; t++) {
        load_stage(t, t);
        asm volatile("cp.async.commit_group;" ::: "memory");
    }

    for (int t = 0; t < KT; t++) {
        asm volatile("cp.async.wait_group %0;" :: "n"(STAGES - 2) : "memory");
        __syncthreads();

        const int tn = t + STAGES - 1;
        if (tn < KT) load_stage(tn, tn % STAGES);
        asm volatile("cp.async.commit_group;" ::: "memory");

        const uint32_t* sA = (const uint32_t*)(sm + (t % STAGES) * STAGE_FLOATS);
        const uint32_t* sB = sA + BM * BK;

        #pragma unroll
        for (int ks = 0; ks < 4; ks++) {
            uint32_t a[4][4], b[4][2];
            const int k = ks * 8 + lc;
            #pragma unroll
            for (int mt = 0; mt < 4; mt++) {
                const int m0 = wm * 64 + mt * 16 + lr;
                const int xm = (m0 & 7) << 2;
                a[mt][0] = sA[m0 * 32 + (k ^ xm)];
                a[mt][1] = sA[(m0 + 8) * 32 + (k ^ xm)];
                a[mt][2] = sA[m0 * 32 + ((k + 4) ^ xm)];
                a[mt][3] = sA[(m0 + 8) * 32 + ((k + 4) ^ xm)];
            }
            #pragma unroll
            for (int nt = 0; nt < 4; nt++) {
                const int n = wn * 32 + nt * 8 + lr;
                const int xn = (n & 7) << 2;
                b[nt][0] = sB[n * 32 + (k ^ xn)];
                b[nt][1] = sB[n * 32 + ((k + 4) ^ xn)];
            }
            #pragma unroll
            for (int mt = 0; mt < 4; mt++)
                #pragma unroll
                for (int nt = 0; nt < 4; nt++)
                    mma_tf32(acc[mt][nt], a[mt], b[nt]);
        }
    }

    // epilogue
    #pragma unroll
    for (int nt = 0; nt < 4; nt++) {
        const int col = bn + wn * 32 + nt * 8 + 2 * lc;
        const float b0 = __ldg(&bias[col]), b1 = __ldg(&bias[col + 1]);
        #pragma unroll
        for (int mt = 0; mt < 4; mt++) {
            const int row0 = bm + wm * 64 + mt * 16 + lr;
            float v0 = acc[mt][nt][0] + b0;
            float v1 = acc[mt][nt][1] + b1;
            float v2 = acc[mt][nt][2] + b0;
            float v3 = acc[mt][nt][3] + b1;
            if (GELU) {
                v0 = 0.5f * v0 * (1.f + erff(v0 * 0.7071067811865475f));
                v1 = 0.5f * v1 * (1.f + erff(v1 * 0.7071067811865475f));
                v2 = 0.5f * v2 * (1.f + erff(v2 * 0.7071067811865475f));
                v3 = 0.5f * v3 * (1.f + erff(v3 * 0.7071067811865475f));
            }
            if (ROUNDOUT) {
                v0 = tf32r(v0); v1 = tf32r(v1); v2 = tf32r(v2); v3 = tf32r(v3);
            }
            *(float2*)&C[(size_t)row0 * Ncols + col]       = make_float2(v0, v1);
            *(float2*)&C[(size_t)(row0 + 8) * Ncols + col] = make_float2(v2, v3);
        }
    }
}

// ---------------- weighted combine ----------------
__global__ void combine_kernel(int N, float* __restrict__ out) {
    const int t = blockIdx.x;
    const int d0 = g_entry_dest[t];
    const int d1 = g_entry_dest[N + t];
    const float p0 = g_entry_prob[t];
    const float p1 = g_entry_prob[N + t];
    const float4* h0 = (d0 >= 0) ? (const float4*)(g_h + (size_t)d0 * H) : nullptr;
    const float4* h1 = (d1 >= 0) ? (const float4*)(g_h + (size_t)d1 * H) : nullptr;
    float4* o = (float4*)(out + (size_t)t * H);
    for (int i = threadIdx.x; i < H / 4; i += blockDim.x) {
        float4 acc = make_float4(0.f, 0.f, 0.f, 0.f);
        if (h0) { float4 v = h0[i]; acc.x += p0*v.x; acc.y += p0*v.y; acc.z += p0*v.z; acc.w += p0*v.w; }
        if (h1) { float4 v = h1[i]; acc.x += p1*v.x; acc.y += p1*v.y; acc.z += p1*v.z; acc.w += p1*v.w; }
        o[i] = acc;
    }
}

// ---------------- launch ----------------
extern "C" void kernel_launch(void* const* d_in, const int* in_sizes, int n_in,
                              void* d_out, int out_size) {
    const float* x  = (const float*)d_in[0];
    const float* rw = (const float*)d_in[1];
    const float* w1 = (const float*)d_in[2];
    const float* b1 = (const float*)d_in[3];
    const float* w2 = (const float*)d_in[4];
    const float* b2 = (const float*)d_in[5];
    float* out = (float*)d_out;

    const int N = in_sizes[0] / H;   // 2048

    float* buf; cudaGetSymbolAddress((void**)&buf, g_buf);
    float* act; cudaGetSymbolAddress((void**)&act, g_act);
    float* hbf; cudaGetSymbolAddress((void**)&hbf, g_h);
    float* w1r; cudaGetSymbolAddress((void**)&w1r, g_w1r);
    float* w2r; cudaGetSymbolAddress((void**)&w2r, g_w2r);

    cudaFuncSetAttribute(gemm_mma<true, true>,
                         cudaFuncAttributeMaxDynamicSharedMemorySize, GEMM_SMEM);
    cudaFuncSetAttribute(gemm_mma<false, false>,
                         cudaFuncAttributeMaxDynamicSharedMemorySize, GEMM_SMEM);

    {   // weight tf32 rounding
        size_t n4 = (size_t)F * H / 4;
        round_tf32<<<(unsigned)((n4 + 255) / 256), 256>>>(w1, w1r, n4);
        round_tf32<<<(unsigned)((n4 + 255) / 256), 256>>>(w2, w2r, n4);
    }

    router_kernel<<<N, 256>>>(x, rw, N);
    assign_kernel<<<1, 256>>>(N);
    dispatch_kernel<<<NSLOT, 256>>>(x);

    // GEMM1: buf[4096,2048] @ w1r^T -> gelu (tf32-rounded) -> act
    gemm_mma<true, true><<<dim3(F / BN, NSLOT / BM), 256, GEMM_SMEM>>>(
        buf, w1r, b1, act, F, H);
    // GEMM2: act[4096,8192] @ w2r^T + b2 -> h (fp32)
    gemm_mma<false, false><<<dim3(H / BN, NSLOT / BM), 256, GEMM_SMEM>>>(
        act, w2r, b2, hbf, H, F);

    combine_kernel<<<N, 256>>>(N, out);
}

// round 5
// speedup vs baseline: 4.5619x; 1.2958x over previous
#include <cuda_runtime.h>
#include <cstdint>
#include <math.h>

#define E 8
#define TOPK 2
#define CAP 512
#define H 2048
#define F 8192
#define NSLOT (E*CAP)   // 4096

// ---------------- scratch (no allocation allowed) ----------------
__device__ float g_buf[(size_t)NSLOT * H];   // dispatch buffer (tf32-rounded)
__device__ float g_act[(size_t)NSLOT * F];   // gelu acts (tf32-rounded)
__device__ float g_h  [(size_t)NSLOT * H];   // expert output fp32
__device__ float g_w1r[(size_t)F * H];       // w1 tf32-rounded
__device__ float g_w2r[(size_t)H * F];       // w2 tf32-rounded
__device__ int   g_entry_expert[2 * 2048];
__device__ float g_entry_prob  [2 * 2048];
__device__ int   g_entry_dest  [2 * 2048];
__device__ int   g_slot_token  [NSLOT];

// ---------------- helpers ----------------
__device__ __forceinline__ uint32_t smem_u32(const void* p) {
    uint32_t a;
    asm("{ .reg .u64 t; cvta.to.shared.u64 t, %1; cvt.u32.u64 %0, t; }"
        : "=r"(a) : "l"(p));
    return a;
}
__device__ __forceinline__ float tf32r(float x) {
    uint32_t u;
    asm("cvt.rna.tf32.f32 %0, %1;" : "=r"(u) : "f"(x));
    return __uint_as_float(u);
}
__device__ __forceinline__ void cp16(uint32_t dst, const void* src) {
    asm volatile("cp.async.cg.shared.global [%0], [%1], 16;"
                 :: "r"(dst), "l"(src) : "memory");
}
__device__ __forceinline__ void mma_tf32(float* c, const uint32_t* a, const uint32_t* b) {
    asm volatile(
        "mma.sync.aligned.m16n8k8.row.col.f32.tf32.tf32.f32 "
        "{%0,%1,%2,%3}, {%4,%5,%6,%7}, {%8,%9}, {%0,%1,%2,%3};"
        : "+f"(c[0]), "+f"(c[1]), "+f"(c[2]), "+f"(c[3])
        : "r"(a[0]), "r"(a[1]), "r"(a[2]), "r"(a[3]), "r"(b[0]), "r"(b[1]));
}

// ---------------- tf32 rounding pass (weights) ----------------
__global__ void round_tf32(const float* __restrict__ src, float* __restrict__ dst,
                           size_t n4) {
    size_t i = (size_t)blockIdx.x * blockDim.x + threadIdx.x;
    if (i < n4) {
        float4 v = ((const float4*)src)[i];
        ((float4*)dst)[i] = make_float4(tf32r(v.x), tf32r(v.y), tf32r(v.z), tf32r(v.w));
    }
}

// ---------------- router ----------------
__global__ void router_kernel(const float* __restrict__ x,
                              const float* __restrict__ rw, int N) {
    const int t = blockIdx.x;
    const int tid = threadIdx.x;
    const int lane = tid & 31, warp = tid >> 5;

    __shared__ float xs[H];
    const float4* xv = (const float4*)(x + (size_t)t * H);
    float4* xsv = (float4*)xs;
    for (int i = tid; i < H / 4; i += 256) xsv[i] = xv[i];
    __syncthreads();

    const float* wr = rw + (size_t)warp * H;
    float s = 0.f;
    for (int i = lane; i < H; i += 32) s += xs[i] * wr[i];
    #pragma unroll
    for (int o = 16; o; o >>= 1) s += __shfl_xor_sync(0xffffffffu, s, o);

    __shared__ float logits[E];
    if (lane == 0) logits[warp] = s;
    __syncthreads();

    if (tid == 0) {
        float m = logits[0];
        #pragma unroll
        for (int e = 1; e < E; e++) m = fmaxf(m, logits[e]);
        float p[E], den = 0.f;
        #pragma unroll
        for (int e = 0; e < E; e++) { p[e] = __expf(logits[e] - m); den += p[e]; }
        float inv = 1.f / den;
        #pragma unroll
        for (int e = 0; e < E; e++) p[e] *= inv;
        int i0 = 0;
        #pragma unroll
        for (int e = 1; e < E; e++) if (p[e] > p[i0]) i0 = e;
        int i1 = (i0 == 0) ? 1 : 0;
        #pragma unroll
        for (int e = 0; e < E; e++) if (e != i0 && p[e] > p[i1]) i1 = e;
        g_entry_expert[t]     = i0; g_entry_prob[t]     = p[i0];
        g_entry_expert[N + t] = i1; g_entry_prob[N + t] = p[i1];
    }
}

// ---------------- capacity scan: warp-per-expert ballot rank ----------------
__global__ void assign_kernel(int N) {
    const int NK = TOPK * N;                    // 4096
    const int tid = threadIdx.x;
    const int lane = tid & 31, warp = tid >> 5; // 8 warps = 8 experts

    __shared__ int se[2 * 2048];
    for (int i = tid; i < NSLOT; i += blockDim.x) g_slot_token[i] = -1;
    for (int i = tid; i < NK; i += blockDim.x) se[i] = g_entry_expert[i];
    __syncthreads();

    if (warp < E) {
        const int e = warp;
        const unsigned lt = (1u << lane) - 1u;
        int cnt = 0;
        for (int base = 0; base < NK; base += 32) {
            const int idx = base + lane;
            const bool match = (idx < NK) && (se[idx] == e);
            const unsigned m = __ballot_sync(0xffffffffu, match);
            if (match) {
                const int pos = cnt + __popc(m & lt);
                if (pos < CAP) {
                    const int d = e * CAP + pos;
                    g_entry_dest[idx] = d;
                    g_slot_token[d] = idx % N;
                } else {
                    g_entry_dest[idx] = -1;
                }
            }
            cnt += __popc(m);
        }
    }
}

// ---------------- gather tokens (tf32-rounded) into dispatch buffer ----------------
__global__ void dispatch_kernel(const float* __restrict__ x) {
    const int slot = blockIdx.x;
    const int t = g_slot_token[slot];
    float4* dst = (float4*)(g_buf + (size_t)slot * H);
    if (t >= 0) {
        const float4* src = (const float4*)(x + (size_t)t * H);
        for (int i = threadIdx.x; i < H / 4; i += blockDim.x) {
            float4 v = src[i];
            dst[i] = make_float4(tf32r(v.x), tf32r(v.y), tf32r(v.z), tf32r(v.w));
        }
    } else {
        const float4 z = make_float4(0.f, 0.f, 0.f, 0.f);
        for (int i = threadIdx.x; i < H / 4; i += blockDim.x) dst[i] = z;
    }
}

// ---------------- TF32 mma.sync GEMM: C = act(A @ B^T + bias) ----------------
// Operands pre-rounded to tf32 in gmem -> no cvt in the hot loop.
// Block 128x128x32, 8 warps (2M x 4N), warp tile 64x32, 3-stage cp.async.
#define BM 128
#define BN 128
#define BK 32
#define STAGES 3
#define STAGE_FLOATS (2 * BM * BK)               // 32KB
#define GEMM_SMEM (STAGES * STAGE_FLOATS * 4)    // 96KB

template<bool GELU, bool ROUNDOUT>
__global__ __launch_bounds__(256, 2)
void gemm_mma(const float* __restrict__ A, const float* __restrict__ B,
              const float* __restrict__ bias, float* __restrict__ C,
              int Ncols, int K) {
    extern __shared__ float sm[];
    const uint32_t sbase = smem_u32(sm);
    const int tid = threadIdx.x, lane = tid & 31, wid = tid >> 5;
    const int wm = wid & 1, wn = wid >> 1;
    const int bm = blockIdx.y * BM, bn = blockIdx.x * BN;
    const int lr = lane >> 2, lc = lane & 3;
    const int KT = K / BK;

    float acc[4][4][4];
    #pragma unroll
    for (int i = 0; i < 4; i++)
        #pragma unroll
        for (int j = 0; j < 4; j++)
            #pragma unroll
            for (int q = 0; q < 4; q++) acc[i][j][q] = 0.f;

    const int lrow = tid >> 3;
    const int lj   = tid & 7;
    auto load_stage = [&](int t, int s) {
        const int k0 = t * BK;
        const uint32_t stA = sbase + s * (STAGE_FLOATS * 4);
        const uint32_t stB = stA + BM * BK * 4;
        #pragma unroll
        for (int l = 0; l < 4; l++) {
            const int row = lrow + l * 32;
            const uint32_t doff = row * 128 + ((lj ^ (row & 7)) << 4);
            cp16(stA + doff, A + (size_t)(bm + row) * K + k0 + lj * 4);
            cp16(stB + doff, B + (size_t)(bn + row) * K + k0 + lj * 4);
        }
    };

    #pragma unroll
    for (int t = 0; t < STAGES - 1; t++) {
        load_stage(t, t);
        asm volatile("cp.async.commit_group;" ::: "memory");
    }

    for (int t = 0; t < KT; t++) {
        asm volatile("cp.async.wait_group %0;" :: "n"(STAGES - 2) : "memory");
        __syncthreads();

        const int tn = t + STAGES - 1;
        if (tn < KT) load_stage(tn, tn % STAGES);
        asm volatile("cp.async.commit_group;" ::: "memory");

        const uint32_t* sA = (const uint32_t*)(sm + (t % STAGES) * STAGE_FLOATS);
        const uint32_t* sB = sA + BM * BK;

        #pragma unroll
        for (int ks = 0; ks < 4; ks++) {
            uint32_t a[4][4], b[4][2];
            const int k = ks * 8 + lc;
            #pragma unroll
            for (int mt = 0; mt < 4; mt++) {
                const int m0 = wm * 64 + mt * 16 + lr;
                const int xm = (m0 & 7) << 2;
                a[mt][0] = sA[m0 * 32 + (k ^ xm)];
                a[mt][1] = sA[(m0 + 8) * 32 + (k ^ xm)];
                a[mt][2] = sA[m0 * 32 + ((k + 4) ^ xm)];
                a[mt][3] = sA[(m0 + 8) * 32 + ((k + 4) ^ xm)];
            }
            #pragma unroll
            for (int nt = 0; nt < 4; nt++) {
                const int n = wn * 32 + nt * 8 + lr;
                const int xn = (n & 7) << 2;
                b[nt][0] = sB[n * 32 + (k ^ xn)];
                b[nt][1] = sB[n * 32 + ((k + 4) ^ xn)];
            }
            #pragma unroll
            for (int mt = 0; mt < 4; mt++)
                #pragma unroll
                for (int nt = 0; nt < 4; nt++)
                    mma_tf32(acc[mt][nt], a[mt], b[nt]);
        }
    }

    // epilogue
    #pragma unroll
    for (int nt = 0; nt < 4; nt++) {
        const int col = bn + wn * 32 + nt * 8 + 2 * lc;
        const float b0 = __ldg(&bias[col]), b1 = __ldg(&bias[col + 1]);
        #pragma unroll
        for (int mt = 0; mt < 4; mt++) {
            const int row0 = bm + wm * 64 + mt * 16 + lr;
            float v0 = acc[mt][nt][0] + b0;
            float v1 = acc[mt][nt][1] + b1;
            float v2 = acc[mt][nt][2] + b0;
            float v3 = acc[mt][nt][3] + b1;
            if (GELU) {
                v0 = 0.5f * v0 * (1.f + erff(v0 * 0.7071067811865475f));
                v1 = 0.5f * v1 * (1.f + erff(v1 * 0.7071067811865475f));
                v2 = 0.5f * v2 * (1.f + erff(v2 * 0.7071067811865475f));
                v3 = 0.5f * v3 * (1.f + erff(v3 * 0.7071067811865475f));
            }
            if (ROUNDOUT) {
                v0 = tf32r(v0); v1 = tf32r(v1); v2 = tf32r(v2); v3 = tf32r(v3);
            }
            *(float2*)&C[(size_t)row0 * Ncols + col]       = make_float2(v0, v1);
            *(float2*)&C[(size_t)(row0 + 8) * Ncols + col] = make_float2(v2, v3);
        }
    }
}

// ---------------- weighted combine ----------------
__global__ void combine_kernel(int N, float* __restrict__ out) {
    const int t = blockIdx.x;
    const int d0 = g_entry_dest[t];
    const int d1 = g_entry_dest[N + t];
    const float p0 = g_entry_prob[t];
    const float p1 = g_entry_prob[N + t];
    const float4* h0 = (d0 >= 0) ? (const float4*)(g_h + (size_t)d0 * H) : nullptr;
    const float4* h1 = (d1 >= 0) ? (const float4*)(g_h + (size_t)d1 * H) : nullptr;
    float4* o = (float4*)(out + (size_t)t * H);
    for (int i = threadIdx.x; i < H / 4; i += blockDim.x) {
        float4 acc = make_float4(0.f, 0.f, 0.f, 0.f);
        if (h0) { float4 v = h0[i]; acc.x += p0*v.x; acc.y += p0*v.y; acc.z += p0*v.z; acc.w += p0*v.w; }
        if (h1) { float4 v = h1[i]; acc.x += p1*v.x; acc.y += p1*v.y; acc.z += p1*v.z; acc.w += p1*v.w; }
        o[i] = acc;
    }
}

// ---------------- launch ----------------
extern "C" void kernel_launch(void* const* d_in, const int* in_sizes, int n_in,
                              void* d_out, int out_size) {
    const float* x  = (const float*)d_in[0];
    const float* rw = (const float*)d_in[1];
    const float* w1 = (const float*)d_in[2];
    const float* b1 = (const float*)d_in[3];
    const float* w2 = (const float*)d_in[4];
    const float* b2 = (const float*)d_in[5];
    float* out = (float*)d_out;

    const int N = in_sizes[0] / H;   // 2048

    float* buf; cudaGetSymbolAddress((void**)&buf, g_buf);
    float* act; cudaGetSymbolAddress((void**)&act, g_act);
    float* hbf; cudaGetSymbolAddress((void**)&hbf, g_h);
    float* w1r; cudaGetSymbolAddress((void**)&w1r, g_w1r);
    float* w2r; cudaGetSymbolAddress((void**)&w2r, g_w2r);

    cudaFuncSetAttribute(gemm_mma<true, true>,
                         cudaFuncAttributeMaxDynamicSharedMemorySize, GEMM_SMEM);
    cudaFuncSetAttribute(gemm_mma<false, false>,
                         cudaFuncAttributeMaxDynamicSharedMemorySize, GEMM_SMEM);

    {   // weight tf32 rounding
        size_t n4 = (size_t)F * H / 4;
        round_tf32<<<(unsigned)((n4 + 255) / 256), 256>>>(w1, w1r, n4);
        round_tf32<<<(unsigned)((n4 + 255) / 256), 256>>>(w2, w2r, n4);
    }

    router_kernel<<<N, 256>>>(x, rw, N);
    assign_kernel<<<1, 256>>>(N);
    dispatch_kernel<<<NSLOT, 256>>>(x);

    // GEMM1: buf[4096,2048] @ w1r^T -> gelu (tf32-rounded) -> act
    gemm_mma<true, true><<<dim3(F / BN, NSLOT / BM), 256, GEMM_SMEM>>>(
        buf, w1r, b1, act, F, H);
    // GEMM2: act[4096,8192] @ w2r^T + b2 -> h (fp32)
    gemm_mma<false, false><<<dim3(H / BN, NSLOT / BM), 256, GEMM_SMEM>>>(
        act, w2r, b2, hbf, H, F);

    combine_kernel<<<N, 256>>>(N, out);
}

// round 6
// speedup vs baseline: 4.5993x; 1.0082x over previous
#include <cuda_runtime.h>
#include <cstdint>
#include <math.h>

#define E 8
#define TOPK 2
#define CAP 512
#define H 2048
#define F 8192
#define NSLOT (E*CAP)   // 4096

// ---------------- scratch (no allocation allowed) ----------------
__device__ float g_buf[(size_t)NSLOT * H];   // dispatch buffer (tf32-rounded)
__device__ float g_act[(size_t)NSLOT * F];   // gelu acts (tf32-rounded)
__device__ float g_h  [(size_t)NSLOT * H];   // expert output fp32
__device__ float g_w1r[(size_t)F * H];       // w1 tf32-rounded
__device__ float g_w2r[(size_t)H * F];       // w2 tf32-rounded
__device__ int   g_entry_expert[2 * 2048];
__device__ float g_entry_prob  [2 * 2048];
__device__ int   g_entry_dest  [2 * 2048];
__device__ int   g_slot_token  [NSLOT];

// ---------------- helpers ----------------
__device__ __forceinline__ uint32_t smem_u32(const void* p) {
    uint32_t a;
    asm("{ .reg .u64 t; cvta.to.shared.u64 t, %1; cvt.u32.u64 %0, t; }"
        : "=r"(a) : "l"(p));
    return a;
}
__device__ __forceinline__ float tf32r(float x) {
    uint32_t u;
    asm("cvt.rna.tf32.f32 %0, %1;" : "=r"(u) : "f"(x));
    return __uint_as_float(u);
}
__device__ __forceinline__ void cp16(uint32_t dst, const void* src) {
    asm volatile("cp.async.cg.shared.global [%0], [%1], 16;"
                 :: "r"(dst), "l"(src) : "memory");
}
__device__ __forceinline__ void mma_tf32(float* c, const uint32_t* a, const uint32_t* b) {
    asm volatile(
        "mma.sync.aligned.m16n8k8.row.col.f32.tf32.tf32.f32 "
        "{%0,%1,%2,%3}, {%4,%5,%6,%7}, {%8,%9}, {%0,%1,%2,%3};"
        : "+f"(c[0]), "+f"(c[1]), "+f"(c[2]), "+f"(c[3])
        : "r"(a[0]), "r"(a[1]), "r"(a[2]), "r"(a[3]), "r"(b[0]), "r"(b[1]));
}

// ---------------- tf32 rounding pass (weights) ----------------
__global__ void round_tf32(const float* __restrict__ src, float* __restrict__ dst,
                           size_t n4) {
    size_t i = (size_t)blockIdx.x * blockDim.x + threadIdx.x;
    if (i < n4) {
        float4 v = ((const float4*)src)[i];
        ((float4*)dst)[i] = make_float4(tf32r(v.x), tf32r(v.y), tf32r(v.z), tf32r(v.w));
    }
}

// ---------------- router ----------------
__global__ void router_kernel(const float* __restrict__ x,
                              const float* __restrict__ rw, int N) {
    const int t = blockIdx.x;
    const int tid = threadIdx.x;
    const int lane = tid & 31, warp = tid >> 5;

    __shared__ float xs[H];
    const float4* xv = (const float4*)(x + (size_t)t * H);
    float4* xsv = (float4*)xs;
    for (int i = tid; i < H / 4; i += 256) xsv[i] = xv[i];
    __syncthreads();

    const float* wr = rw + (size_t)warp * H;
    float s = 0.f;
    for (int i = lane; i < H; i += 32) s += xs[i] * wr[i];
    #pragma unroll
    for (int o = 16; o; o >>= 1) s += __shfl_xor_sync(0xffffffffu, s, o);

    __shared__ float logits[E];
    if (lane == 0) logits[warp] = s;
    __syncthreads();

    if (tid == 0) {
        float m = logits[0];
        #pragma unroll
        for (int e = 1; e < E; e++) m = fmaxf(m, logits[e]);
        float p[E], den = 0.f;
        #pragma unroll
        for (int e = 0; e < E; e++) { p[e] = __expf(logits[e] - m); den += p[e]; }
        float inv = 1.f / den;
        #pragma unroll
        for (int e = 0; e < E; e++) p[e] *= inv;
        int i0 = 0;
        #pragma unroll
        for (int e = 1; e < E; e++) if (p[e] > p[i0]) i0 = e;
        int i1 = (i0 == 0) ? 1 : 0;
        #pragma unroll
        for (int e = 0; e < E; e++) if (e != i0 && p[e] > p[i1]) i1 = e;
        g_entry_expert[t]     = i0; g_entry_prob[t]     = p[i0];
        g_entry_expert[N + t] = i1; g_entry_prob[N + t] = p[i1];
    }
}

// ---------------- capacity scan: warp-per-expert ballot rank ----------------
__global__ void assign_kernel(int N) {
    const int NK = TOPK * N;                    // 4096
    const int tid = threadIdx.x;
    const int lane = tid & 31, warp = tid >> 5; // 8 warps = 8 experts

    __shared__ int se[2 * 2048];
    for (int i = tid; i < NSLOT; i += blockDim.x) g_slot_token[i] = -1;
    for (int i = tid; i < NK; i += blockDim.x) se[i] = g_entry_expert[i];
    __syncthreads();

    if (warp < E) {
        const int e = warp;
        const unsigned lt = (1u << lane) - 1u;
        int cnt = 0;
        for (int base = 0; base < NK; base += 32) {
            const int idx = base + lane;
            const bool match = (idx < NK) && (se[idx] == e);
            const unsigned m = __ballot_sync(0xffffffffu, match);
            if (match) {
                const int pos = cnt + __popc(m & lt);
                if (pos < CAP) {
                    const int d = e * CAP + pos;
                    g_entry_dest[idx] = d;
                    g_slot_token[d] = idx % N;
                } else {
                    g_entry_dest[idx] = -1;
                }
            }
            cnt += __popc(m);
        }
    }
}

// ---------------- gather tokens (tf32-rounded) into dispatch buffer ----------------
__global__ void dispatch_kernel(const float* __restrict__ x) {
    const int slot = blockIdx.x;
    const int t = g_slot_token[slot];
    float4* dst = (float4*)(g_buf + (size_t)slot * H);
    if (t >= 0) {
        const float4* src = (const float4*)(x + (size_t)t * H);
        for (int i = threadIdx.x; i < H / 4; i += blockDim.x) {
            float4 v = src[i];
            dst[i] = make_float4(tf32r(v.x), tf32r(v.y), tf32r(v.z), tf32r(v.w));
        }
    } else {
        const float4 z = make_float4(0.f, 0.f, 0.f, 0.f);
        for (int i = threadIdx.x; i < H / 4; i += blockDim.x) dst[i] = z;
    }
}

// ---------------- TF32 mma.sync GEMM: C = act(A @ B^T + bias) ----------------
// Operands pre-rounded to tf32 in gmem -> no cvt in the hot loop.
// Block 128x256x32, 8 warps (2M x 4N), warp tile 64x64, 3-stage cp.async.
// Smem [row][k] with XOR swizzle: float (r,k) at r*32 + (k ^ ((r&7)<<2)).
#define BM 128
#define BN 256
#define BK 32
#define STAGES 3
#define STAGE_FLOATS ((BM + BN) * BK)            // 12288 floats = 48KB
#define GEMM_SMEM (STAGES * STAGE_FLOATS * 4)    // 144KB

template<bool GELU, bool ROUNDOUT>
__global__ __launch_bounds__(256, 1)
void gemm_mma(const float* __restrict__ A, const float* __restrict__ B,
              const float* __restrict__ bias, float* __restrict__ C,
              int Ncols, int K) {
    extern __shared__ float sm[];
    const uint32_t sbase = smem_u32(sm);
    const int tid = threadIdx.x, lane = tid & 31, wid = tid >> 5;
    const int wm = wid & 1, wn = wid >> 1;       // 2(M) x 4(N), warp tile 64x64
    const int bm = blockIdx.y * BM, bn = blockIdx.x * BN;
    const int lr = lane >> 2, lc = lane & 3;
    const int KT = K / BK;

    float acc[4][8][4];
    #pragma unroll
    for (int i = 0; i < 4; i++)
        #pragma unroll
        for (int j = 0; j < 8; j++)
            #pragma unroll
            for (int q = 0; q < 4; q++) acc[i][j][q] = 0.f;

    const int lrow = tid >> 3;        // 0..31
    const int lj   = tid & 7;         // 16B chunk in 128B row
    auto load_stage = [&](int t, int s) {
        const int k0 = t * BK;
        const uint32_t stA = sbase + s * (STAGE_FLOATS * 4);
        const uint32_t stB = stA + BM * BK * 4;
        #pragma unroll
        for (int l = 0; l < 4; l++) {
            const int row = lrow + l * 32;
            const uint32_t doff = row * 128 + ((lj ^ (row & 7)) << 4);
            cp16(stA + doff, A + (size_t)(bm + row) * K + k0 + lj * 4);
        }
        #pragma unroll
        for (int l = 0; l < 8; l++) {
            const int row = lrow + l * 32;
            const uint32_t doff = row * 128 + ((lj ^ (row & 7)) << 4);
            cp16(stB + doff, B + (size_t)(bn + row) * K + k0 + lj * 4);
        }
    };

    #pragma unroll
    for (int t = 0; t < STAGES - 1; t++) {
        load_stage(t, t);
        asm volatile("cp.async.commit_group;" ::: "memory");
    }

    for (int t = 0; t < KT; t++) {
        asm volatile("cp.async.wait_group %0;" :: "n"(STAGES - 2) : "memory");
        __syncthreads();

        const int tn = t + STAGES - 1;
        if (tn < KT) load_stage(tn, tn % STAGES);
        asm volatile("cp.async.commit_group;" ::: "memory");

        const uint32_t* sA = (const uint32_t*)(sm + (t % STAGES) * STAGE_FLOATS);
        const uint32_t* sB = sA + BM * BK;

        #pragma unroll
        for (int ks = 0; ks < 4; ks++) {
            uint32_t a[4][4], b[8][2];
            const int k = ks * 8 + lc;
            #pragma unroll
            for (int mt = 0; mt < 4; mt++) {
                const int m0 = wm * 64 + mt * 16 + lr;
                const int xm = (m0 & 7) << 2;
                a[mt][0] = sA[m0 * 32 + (k ^ xm)];
                a[mt][1] = sA[(m0 + 8) * 32 + (k ^ xm)];
                a[mt][2] = sA[m0 * 32 + ((k + 4) ^ xm)];
                a[mt][3] = sA[(m0 + 8) * 32 + ((k + 4) ^ xm)];
            }
            #pragma unroll
            for (int nt = 0; nt < 8; nt++) {
                const int n = wn * 64 + nt * 8 + lr;
                const int xn = (n & 7) << 2;
                b[nt][0] = sB[n * 32 + (k ^ xn)];
                b[nt][1] = sB[n * 32 + ((k + 4) ^ xn)];
            }
            #pragma unroll
            for (int mt = 0; mt < 4; mt++)
                #pragma unroll
                for (int nt = 0; nt < 8; nt++)
                    mma_tf32(acc[mt][nt], a[mt], b[nt]);
        }
    }

    // epilogue
    #pragma unroll
    for (int nt = 0; nt < 8; nt++) {
        const int col = bn + wn * 64 + nt * 8 + 2 * lc;
        const float b0 = __ldg(&bias[col]), b1 = __ldg(&bias[col + 1]);
        #pragma unroll
        for (int mt = 0; mt < 4; mt++) {
            const int row0 = bm + wm * 64 + mt * 16 + lr;
            float v0 = acc[mt][nt][0] + b0;
            float v1 = acc[mt][nt][1] + b1;
            float v2 = acc[mt][nt][2] + b0;
            float v3 = acc[mt][nt][3] + b1;
            if (GELU) {
                v0 = 0.5f * v0 * (1.f + erff(v0 * 0.7071067811865475f));
                v1 = 0.5f * v1 * (1.f + erff(v1 * 0.7071067811865475f));
                v2 = 0.5f * v2 * (1.f + erff(v2 * 0.7071067811865475f));
                v3 = 0.5f * v3 * (1.f + erff(v3 * 0.7071067811865475f));
            }
            if (ROUNDOUT) {
                v0 = tf32r(v0); v1 = tf32r(v1); v2 = tf32r(v2); v3 = tf32r(v3);
            }
            *(float2*)&C[(size_t)row0 * Ncols + col]       = make_float2(v0, v1);
            *(float2*)&C[(size_t)(row0 + 8) * Ncols + col] = make_float2(v2, v3);
        }
    }
}

// ---------------- weighted combine ----------------
__global__ void combine_kernel(int N, float* __restrict__ out) {
    const int t = blockIdx.x;
    const int d0 = g_entry_dest[t];
    const int d1 = g_entry_dest[N + t];
    const float p0 = g_entry_prob[t];
    const float p1 = g_entry_prob[N + t];
    const float4* h0 = (d0 >= 0) ? (const float4*)(g_h + (size_t)d0 * H) : nullptr;
    const float4* h1 = (d1 >= 0) ? (const float4*)(g_h + (size_t)d1 * H) : nullptr;
    float4* o = (float4*)(out + (size_t)t * H);
    for (int i = threadIdx.x; i < H / 4; i += blockDim.x) {
        float4 acc = make_float4(0.f, 0.f, 0.f, 0.f);
        if (h0) { float4 v = h0[i]; acc.x += p0*v.x; acc.y += p0*v.y; acc.z += p0*v.z; acc.w += p0*v.w; }
        if (h1) { float4 v = h1[i]; acc.x += p1*v.x; acc.y += p1*v.y; acc.z += p1*v.z; acc.w += p1*v.w; }
        o[i] = acc;
    }
}

// ---------------- launch ----------------
extern "C" void kernel_launch(void* const* d_in, const int* in_sizes, int n_in,
                              void* d_out, int out_size) {
    const float* x  = (const float*)d_in[0];
    const float* rw = (const float*)d_in[1];
    const float* w1 = (const float*)d_in[2];
    const float* b1 = (const float*)d_in[3];
    const float* w2 = (const float*)d_in[4];
    const float* b2 = (const float*)d_in[5];
    float* out = (float*)d_out;

    const int N = in_sizes[0] / H;   // 2048

    float* buf; cudaGetSymbolAddress((void**)&buf, g_buf);
    float* act; cudaGetSymbolAddress((void**)&act, g_act);
    float* hbf; cudaGetSymbolAddress((void**)&hbf, g_h);
    float* w1r; cudaGetSymbolAddress((void**)&w1r, g_w1r);
    float* w2r; cudaGetSymbolAddress((void**)&w2r, g_w2r);

    cudaFuncSetAttribute(gemm_mma<true, true>,
                         cudaFuncAttributeMaxDynamicSharedMemorySize, GEMM_SMEM);
    cudaFuncSetAttribute(gemm_mma<false, false>,
                         cudaFuncAttributeMaxDynamicSharedMemorySize, GEMM_SMEM);

    {   // weight tf32 rounding
        size_t n4 = (size_t)F * H / 4;
        round_tf32<<<(unsigned)((n4 + 255) / 256), 256>>>(w1, w1r, n4);
        round_tf32<<<(unsigned)((n4 + 255) / 256), 256>>>(w2, w2r, n4);
    }

    router_kernel<<<N, 256>>>(x, rw, N);
    assign_kernel<<<1, 256>>>(N);
    dispatch_kernel<<<NSLOT, 256>>>(x);

    // GEMM1: buf[4096,2048] @ w1r^T -> gelu (tf32-rounded) -> act
    gemm_mma<true, true><<<dim3(F / BN, NSLOT / BM), 256, GEMM_SMEM>>>(
        buf, w1r, b1, act, F, H);
    // GEMM2: act[4096,8192] @ w2r^T + b2 -> h (fp32)
    gemm_mma<false, false><<<dim3(H / BN, NSLOT / BM), 256, GEMM_SMEM>>>(
        act, w2r, b2, hbf, H, F);

    combine_kernel<<<N, 256>>>(N, out);
}

// round 7
// speedup vs baseline: 5.9830x; 1.3008x over previous
#include <cuda_runtime.h>
#include <cuda_fp16.h>
#include <cstdint>
#include <math.h>

#define E 8
#define TOPK 2
#define CAP 512
#define H 2048
#define F 8192
#define NSLOT (E*CAP)   // 4096

// ---------------- scratch (no allocation allowed) ----------------
__device__ __half g_bufh[(size_t)NSLOT * H];  // dispatch buffer fp16
__device__ __half g_acth[(size_t)NSLOT * F];  // gelu acts fp16
__device__ __half g_w1h[(size_t)F * H];       // w1 fp16
__device__ __half g_w2h[(size_t)H * F];       // w2 fp16
__device__ float  g_h[(size_t)NSLOT * H];     // expert output fp32
__device__ int    g_entry_expert[2 * 2048];
__device__ float  g_entry_prob  [2 * 2048];
__device__ int    g_entry_dest  [2 * 2048];
__device__ int    g_slot_token  [NSLOT];

// ---------------- helpers ----------------
__device__ __forceinline__ uint32_t smem_u32(const void* p) {
    uint32_t a;
    asm("{ .reg .u64 t; cvta.to.shared.u64 t, %1; cvt.u32.u64 %0, t; }"
        : "=r"(a) : "l"(p));
    return a;
}
__device__ __forceinline__ void cp8(uint32_t dst, const void* src) {
    asm volatile("cp.async.ca.shared.global [%0], [%1], 8;"
                 :: "r"(dst), "l"(src) : "memory");
}
__device__ __forceinline__ void mma_f16(float* c, const uint32_t* a, const uint32_t* b) {
    asm volatile(
        "mma.sync.aligned.m16n8k16.row.col.f32.f16.f16.f32 "
        "{%0,%1,%2,%3}, {%4,%5,%6,%7}, {%8,%9}, {%0,%1,%2,%3};"
        : "+f"(c[0]), "+f"(c[1]), "+f"(c[2]), "+f"(c[3])
        : "r"(a[0]), "r"(a[1]), "r"(a[2]), "r"(a[3]), "r"(b[0]), "r"(b[1]));
}

// ---------------- fp32 -> fp16 conversion pass (weights) ----------------
__global__ void tohalf(const float* __restrict__ src, __half* __restrict__ dst,
                       size_t n4) {
    size_t i = (size_t)blockIdx.x * blockDim.x + threadIdx.x;
    if (i < n4) {
        float4 v = ((const float4*)src)[i];
        ((__half2*)dst)[2 * i]     = __floats2half2_rn(v.x, v.y);
        ((__half2*)dst)[2 * i + 1] = __floats2half2_rn(v.z, v.w);
    }
}

// ---------------- router ----------------
__global__ void router_kernel(const float* __restrict__ x,
                              const float* __restrict__ rw, int N) {
    const int t = blockIdx.x;
    const int tid = threadIdx.x;
    const int lane = tid & 31, warp = tid >> 5;

    __shared__ float xs[H];
    const float4* xv = (const float4*)(x + (size_t)t * H);
    float4* xsv = (float4*)xs;
    for (int i = tid; i < H / 4; i += 256) xsv[i] = xv[i];
    __syncthreads();

    const float* wr = rw + (size_t)warp * H;
    float s = 0.f;
    for (int i = lane; i < H; i += 32) s += xs[i] * wr[i];
    #pragma unroll
    for (int o = 16; o; o >>= 1) s += __shfl_xor_sync(0xffffffffu, s, o);

    __shared__ float logits[E];
    if (lane == 0) logits[warp] = s;
    __syncthreads();

    if (tid == 0) {
        float m = logits[0];
        #pragma unroll
        for (int e = 1; e < E; e++) m = fmaxf(m, logits[e]);
        float p[E], den = 0.f;
        #pragma unroll
        for (int e = 0; e < E; e++) { p[e] = __expf(logits[e] - m); den += p[e]; }
        float inv = 1.f / den;
        #pragma unroll
        for (int e = 0; e < E; e++) p[e] *= inv;
        int i0 = 0;
        #pragma unroll
        for (int e = 1; e < E; e++) if (p[e] > p[i0]) i0 = e;
        int i1 = (i0 == 0) ? 1 : 0;
        #pragma unroll
        for (int e = 0; e < E; e++) if (e != i0 && p[e] > p[i1]) i1 = e;
        g_entry_expert[t]     = i0; g_entry_prob[t]     = p[i0];
        g_entry_expert[N + t] = i1; g_entry_prob[N + t] = p[i1];
    }
}

// ---------------- capacity scan: warp-per-expert ballot rank ----------------
__global__ void assign_kernel(int N) {
    const int NK = TOPK * N;                    // 4096
    const int tid = threadIdx.x;
    const int lane = tid & 31, warp = tid >> 5;

    __shared__ int se[2 * 2048];
    for (int i = tid; i < NSLOT; i += blockDim.x) g_slot_token[i] = -1;
    for (int i = tid; i < NK; i += blockDim.x) se[i] = g_entry_expert[i];
    __syncthreads();

    if (warp < E) {
        const int e = warp;
        const unsigned lt = (1u << lane) - 1u;
        int cnt = 0;
        for (int base = 0; base < NK; base += 32) {
            const int idx = base + lane;
            const bool match = (idx < NK) && (se[idx] == e);
            const unsigned m = __ballot_sync(0xffffffffu, match);
            if (match) {
                const int pos = cnt + __popc(m & lt);
                if (pos < CAP) {
                    const int d = e * CAP + pos;
                    g_entry_dest[idx] = d;
                    g_slot_token[d] = idx % N;
                } else {
                    g_entry_dest[idx] = -1;
                }
            }
            cnt += __popc(m);
        }
    }
}

// ---------------- gather tokens (fp16) into dispatch buffer ----------------
__global__ void dispatch_kernel(const float* __restrict__ x) {
    const int slot = blockIdx.x;
    const int t = g_slot_token[slot];
    __half2* dst = (__half2*)(g_bufh + (size_t)slot * H);
    if (t >= 0) {
        const float4* src = (const float4*)(x + (size_t)t * H);
        for (int i = threadIdx.x; i < H / 4; i += blockDim.x) {
            float4 v = src[i];
            dst[2 * i]     = __floats2half2_rn(v.x, v.y);
            dst[2 * i + 1] = __floats2half2_rn(v.z, v.w);
        }
    } else {
        const __half2 z = __floats2half2_rn(0.f, 0.f);
        for (int i = threadIdx.x; i < H / 4; i += blockDim.x) {
            dst[2 * i] = z; dst[2 * i + 1] = z;
        }
    }
}

// ---------------- FP16 mma.sync GEMM: C = act(A @ B^T + bias) ----------------
// A row-major [M,K] fp16, B row-major [N,K] fp16. Block 128x256x32, 8 warps
// (2M x 4N), warp tile 64x64 (4x8 m16n8k16). 4-stage cp.async pipeline.
// Smem rows of 32 fp16 (64B = 8 chunks of 8B); chunk c of row r stored at
// chunk index c ^ (r&7)  -> conflict-free fragment LDS.32, contiguous cp.async.
#define BM 128
#define BN 256
#define BK 32
#define STAGES 4
#define STAGE_BYTES ((BM + BN) * BK * 2)         // 24576
#define GEMM_SMEM (STAGES * STAGE_BYTES)         // 96KB

template<bool GELU, typename CT>
__global__ __launch_bounds__(256, 1)
void gemm_h(const __half* __restrict__ A, const __half* __restrict__ B,
            const float* __restrict__ bias, CT* __restrict__ C,
            int Ncols, int K) {
    extern __shared__ char smraw[];
    const uint32_t sbase = smem_u32(smraw);
    const int tid = threadIdx.x, lane = tid & 31, wid = tid >> 5;
    const int wm = wid & 1, wn = wid >> 1;       // 2(M) x 4(N), warp tile 64x64
    const int bm = blockIdx.y * BM, bn = blockIdx.x * BN;
    const int lr = lane >> 2, lc = lane & 3;
    const int KT = K / BK;

    float acc[4][8][4];
    #pragma unroll
    for (int i = 0; i < 4; i++)
        #pragma unroll
        for (int j = 0; j < 8; j++)
            #pragma unroll
            for (int q = 0; q < 4; q++) acc[i][j][q] = 0.f;

    const int lrow = tid >> 3;        // 0..31
    const int lch  = tid & 7;         // 8B chunk in 64B row
    auto load_stage = [&](int t, int s) {
        const int k0 = t * BK;
        const uint32_t stA = sbase + s * STAGE_BYTES;
        const uint32_t stB = stA + BM * BK * 2;
        #pragma unroll
        for (int l = 0; l < 4; l++) {
            const int row = lrow + l * 32;
            const uint32_t doff = row * 64 + ((lch ^ (row & 7)) << 3);
            cp8(stA + doff, A + (size_t)(bm + row) * K + k0 + lch * 4);
        }
        #pragma unroll
        for (int l = 0; l < 8; l++) {
            const int row = lrow + l * 32;
            const uint32_t doff = row * 64 + ((lch ^ (row & 7)) << 3);
            cp8(stB + doff, B + (size_t)(bn + row) * K + k0 + lch * 4);
        }
    };

    #pragma unroll
    for (int t = 0; t < STAGES - 1; t++) {
        load_stage(t, t);
        asm volatile("cp.async.commit_group;" ::: "memory");
    }

    for (int t = 0; t < KT; t++) {
        asm volatile("cp.async.wait_group %0;" :: "n"(STAGES - 2) : "memory");
        __syncthreads();

        const int tn = t + STAGES - 1;
        if (tn < KT) load_stage(tn, tn % STAGES);
        asm volatile("cp.async.commit_group;" ::: "memory");

        const uint32_t* sA = (const uint32_t*)(smraw + (size_t)(t % STAGES) * STAGE_BYTES);
        const uint32_t* sB = sA + BM * 16;       // 16 u32 words per row

        // word w (0..15) of row r lives at u32 index r*16 + ((w>>1)^(r&7))*2 + (w&1)
        #pragma unroll
        for (int ks = 0; ks < 2; ks++) {         // two k16 steps per BK=32
            uint32_t a[4][4], b[8][2];
            const int w0 = ks * 8 + lc;          // k words lc and lc+4
            const int w1 = w0 + 4;
            #pragma unroll
            for (int mt = 0; mt < 4; mt++) {
                const int m0 = wm * 64 + mt * 16 + lr;
                const int xr = m0 & 7;
                const int i0 = m0 * 16 + (((w0 >> 1) ^ xr) << 1) + (w0 & 1);
                const int i1 = m0 * 16 + (((w1 >> 1) ^ xr) << 1) + (w1 & 1);
                a[mt][0] = sA[i0];
                a[mt][1] = sA[i0 + 128];         // row m0+8, same swizzle
                a[mt][2] = sA[i1];
                a[mt][3] = sA[i1 + 128];
            }
            #pragma unroll
            for (int nt = 0; nt < 8; nt++) {
                const int n = wn * 64 + nt * 8 + lr;
                const int xr = n & 7;
                b[nt][0] = sB[n * 16 + (((w0 >> 1) ^ xr) << 1) + (w0 & 1)];
                b[nt][1] = sB[n * 16 + (((w1 >> 1) ^ xr) << 1) + (w1 & 1)];
            }
            #pragma unroll
            for (int mt = 0; mt < 4; mt++)
                #pragma unroll
                for (int nt = 0; nt < 8; nt++)
                    mma_f16(acc[mt][nt], a[mt], b[nt]);
        }
    }

    // epilogue: bias (+GELU); CT = __half (GEMM1) or float (GEMM2)
    #pragma unroll
    for (int nt = 0; nt < 8; nt++) {
        const int col = bn + wn * 64 + nt * 8 + 2 * lc;
        const float b0 = __ldg(&bias[col]), b1 = __ldg(&bias[col + 1]);
        #pragma unroll
        for (int mt = 0; mt < 4; mt++) {
            const int row0 = bm + wm * 64 + mt * 16 + lr;
            float v0 = acc[mt][nt][0] + b0;
            float v1 = acc[mt][nt][1] + b1;
            float v2 = acc[mt][nt][2] + b0;
            float v3 = acc[mt][nt][3] + b1;
            if (GELU) {
                v0 = 0.5f * v0 * (1.f + erff(v0 * 0.7071067811865475f));
                v1 = 0.5f * v1 * (1.f + erff(v1 * 0.7071067811865475f));
                v2 = 0.5f * v2 * (1.f + erff(v2 * 0.7071067811865475f));
                v3 = 0.5f * v3 * (1.f + erff(v3 * 0.7071067811865475f));
            }
            if (sizeof(CT) == 2) {
                __half2* c0 = (__half2*)((__half*)C + (size_t)row0 * Ncols + col);
                __half2* c1 = (__half2*)((__half*)C + (size_t)(row0 + 8) * Ncols + col);
                *c0 = __floats2half2_rn(v0, v1);
                *c1 = __floats2half2_rn(v2, v3);
            } else {
                *(float2*)((float*)C + (size_t)row0 * Ncols + col)       = make_float2(v0, v1);
                *(float2*)((float*)C + (size_t)(row0 + 8) * Ncols + col) = make_float2(v2, v3);
            }
        }
    }
}

// ---------------- weighted combine ----------------
__global__ void combine_kernel(int N, float* __restrict__ out) {
    const int t = blockIdx.x;
    const int d0 = g_entry_dest[t];
    const int d1 = g_entry_dest[N + t];
    const float p0 = g_entry_prob[t];
    const float p1 = g_entry_prob[N + t];
    const float4* h0 = (d0 >= 0) ? (const float4*)(g_h + (size_t)d0 * H) : nullptr;
    const float4* h1 = (d1 >= 0) ? (const float4*)(g_h + (size_t)d1 * H) : nullptr;
    float4* o = (float4*)(out + (size_t)t * H);
    for (int i = threadIdx.x; i < H / 4; i += blockDim.x) {
        float4 acc = make_float4(0.f, 0.f, 0.f, 0.f);
        if (h0) { float4 v = h0[i]; acc.x += p0*v.x; acc.y += p0*v.y; acc.z += p0*v.z; acc.w += p0*v.w; }
        if (h1) { float4 v = h1[i]; acc.x += p1*v.x; acc.y += p1*v.y; acc.z += p1*v.z; acc.w += p1*v.w; }
        o[i] = acc;
    }
}

// ---------------- launch ----------------
extern "C" void kernel_launch(void* const* d_in, const int* in_sizes, int n_in,
                              void* d_out, int out_size) {
    const float* x  = (const float*)d_in[0];
    const float* rw = (const float*)d_in[1];
    const float* w1 = (const float*)d_in[2];
    const float* b1 = (const float*)d_in[3];
    const float* w2 = (const float*)d_in[4];
    const float* b2 = (const float*)d_in[5];
    float* out = (float*)d_out;

    const int N = in_sizes[0] / H;   // 2048

    __half* bufh; cudaGetSymbolAddress((void**)&bufh, g_bufh);
    __half* acth; cudaGetSymbolAddress((void**)&acth, g_acth);
    __half* w1h;  cudaGetSymbolAddress((void**)&w1h, g_w1h);
    __half* w2h;  cudaGetSymbolAddress((void**)&w2h, g_w2h);
    float*  hbf;  cudaGetSymbolAddress((void**)&hbf, g_h);

    cudaFuncSetAttribute(gemm_h<true, __half>,
                         cudaFuncAttributeMaxDynamicSharedMemorySize, GEMM_SMEM);
    cudaFuncSetAttribute(gemm_h<false, float>,
                         cudaFuncAttributeMaxDynamicSharedMemorySize, GEMM_SMEM);

    {   // weight fp16 conversion
        size_t n4 = (size_t)F * H / 4;
        tohalf<<<(unsigned)((n4 + 255) / 256), 256>>>(w1, w1h, n4);
        tohalf<<<(unsigned)((n4 + 255) / 256), 256>>>(w2, w2h, n4);
    }

    router_kernel<<<N, 256>>>(x, rw, N);
    assign_kernel<<<1, 256>>>(N);
    dispatch_kernel<<<NSLOT, 256>>>(x);

    // GEMM1: buf[4096,2048] @ w1h^T -> gelu -> act (fp16)
    gemm_h<true, __half><<<dim3(F / BN, NSLOT / BM), 256, GEMM_SMEM>>>(
        bufh, w1h, b1, acth, F, H);
    // GEMM2: act[4096,8192] @ w2h^T + b2 -> h (fp32)
    gemm_h<false, float><<<dim3(H / BN, NSLOT / BM), 256, GEMM_SMEM>>>(
        acth, w2h, b2, hbf, H, F);

    combine_kernel<<<N, 256>>>(N, out);
}

// round 8
// speedup vs baseline: 6.4408x; 1.0765x over previous
#include <cuda_runtime.h>
#include <cuda_fp16.h>
#include <cstdint>
#include <math.h>

#define E 8
#define TOPK 2
#define CAP 512
#define H 2048
#define F 8192
#define NSLOT (E*CAP)   // 4096

// ---------------- scratch (no allocation allowed) ----------------
__device__ __half g_bufh[(size_t)NSLOT * H];  // dispatch buffer fp16
__device__ __half g_acth[(size_t)NSLOT * F];  // gelu acts fp16
__device__ __half g_w1h[(size_t)F * H];       // w1 fp16
__device__ __half g_w2h[(size_t)H * F];       // w2 fp16
__device__ float  g_h[(size_t)NSLOT * H];     // expert output fp32
__device__ int    g_entry_expert[2 * 2048];
__device__ float  g_entry_prob  [2 * 2048];
__device__ int    g_entry_dest  [2 * 2048];
__device__ int    g_slot_token  [NSLOT];

// ---------------- helpers ----------------
__device__ __forceinline__ uint32_t smem_u32(const void* p) {
    uint32_t a;
    asm("{ .reg .u64 t; cvta.to.shared.u64 t, %1; cvt.u32.u64 %0, t; }"
        : "=r"(a) : "l"(p));
    return a;
}
__device__ __forceinline__ void cp8(uint32_t dst, const void* src) {
    asm volatile("cp.async.ca.shared.global [%0], [%1], 8;"
                 :: "r"(dst), "l"(src) : "memory");
}
__device__ __forceinline__ void ldsm_x4(uint32_t* r, uint32_t addr) {
    asm volatile("ldmatrix.sync.aligned.m8n8.x4.shared.b16 {%0,%1,%2,%3}, [%4];"
                 : "=r"(r[0]), "=r"(r[1]), "=r"(r[2]), "=r"(r[3]) : "r"(addr));
}
__device__ __forceinline__ void mma_f16(float* c, const uint32_t* a, const uint32_t* b) {
    asm volatile(
        "mma.sync.aligned.m16n8k16.row.col.f32.f16.f16.f32 "
        "{%0,%1,%2,%3}, {%4,%5,%6,%7}, {%8,%9}, {%0,%1,%2,%3};"
        : "+f"(c[0]), "+f"(c[1]), "+f"(c[2]), "+f"(c[3])
        : "r"(a[0]), "r"(a[1]), "r"(a[2]), "r"(a[3]), "r"(b[0]), "r"(b[1]));
}

// ---------------- fp32 -> fp16 conversion pass (weights) ----------------
__global__ void tohalf(const float* __restrict__ src, __half* __restrict__ dst,
                       size_t n4) {
    size_t i = (size_t)blockIdx.x * blockDim.x + threadIdx.x;
    if (i < n4) {
        float4 v = ((const float4*)src)[i];
        ((__half2*)dst)[2 * i]     = __floats2half2_rn(v.x, v.y);
        ((__half2*)dst)[2 * i + 1] = __floats2half2_rn(v.z, v.w);
    }
}

// ---------------- router ----------------
__global__ void router_kernel(const float* __restrict__ x,
                              const float* __restrict__ rw, int N) {
    const int t = blockIdx.x;
    const int tid = threadIdx.x;
    const int lane = tid & 31, warp = tid >> 5;

    __shared__ float xs[H];
    const float4* xv = (const float4*)(x + (size_t)t * H);
    float4* xsv = (float4*)xs;
    for (int i = tid; i < H / 4; i += 256) xsv[i] = xv[i];
    __syncthreads();

    const float* wr = rw + (size_t)warp * H;
    float s = 0.f;
    for (int i = lane; i < H; i += 32) s += xs[i] * wr[i];
    #pragma unroll
    for (int o = 16; o; o >>= 1) s += __shfl_xor_sync(0xffffffffu, s, o);

    __shared__ float logits[E];
    if (lane == 0) logits[warp] = s;
    __syncthreads();

    if (tid == 0) {
        float m = logits[0];
        #pragma unroll
        for (int e = 1; e < E; e++) m = fmaxf(m, logits[e]);
        float p[E], den = 0.f;
        #pragma unroll
        for (int e = 0; e < E; e++) { p[e] = __expf(logits[e] - m); den += p[e]; }
        float inv = 1.f / den;
        #pragma unroll
        for (int e = 0; e < E; e++) p[e] *= inv;
        int i0 = 0;
        #pragma unroll
        for (int e = 1; e < E; e++) if (p[e] > p[i0]) i0 = e;
        int i1 = (i0 == 0) ? 1 : 0;
        #pragma unroll
        for (int e = 0; e < E; e++) if (e != i0 && p[e] > p[i1]) i1 = e;
        g_entry_expert[t]     = i0; g_entry_prob[t]     = p[i0];
        g_entry_expert[N + t] = i1; g_entry_prob[N + t] = p[i1];
    }
}

// ---------------- capacity scan: warp-per-expert ballot rank ----------------
__global__ void assign_kernel(int N) {
    const int NK = TOPK * N;                    // 4096
    const int tid = threadIdx.x;
    const int lane = tid & 31, warp = tid >> 5;

    __shared__ int se[2 * 2048];
    for (int i = tid; i < NSLOT; i += blockDim.x) g_slot_token[i] = -1;
    for (int i = tid; i < NK; i += blockDim.x) se[i] = g_entry_expert[i];
    __syncthreads();

    if (warp < E) {
        const int e = warp;
        const unsigned lt = (1u << lane) - 1u;
        int cnt = 0;
        for (int base = 0; base < NK; base += 32) {
            const int idx = base + lane;
            const bool match = (idx < NK) && (se[idx] == e);
            const unsigned m = __ballot_sync(0xffffffffu, match);
            if (match) {
                const int pos = cnt + __popc(m & lt);
                if (pos < CAP) {
                    const int d = e * CAP + pos;
                    g_entry_dest[idx] = d;
                    g_slot_token[d] = idx % N;
                } else {
                    g_entry_dest[idx] = -1;
                }
            }
            cnt += __popc(m);
        }
    }
}

// ---------------- gather tokens (fp16) into dispatch buffer ----------------
__global__ void dispatch_kernel(const float* __restrict__ x) {
    const int slot = blockIdx.x;
    const int t = g_slot_token[slot];
    __half2* dst = (__half2*)(g_bufh + (size_t)slot * H);
    if (t >= 0) {
        const float4* src = (const float4*)(x + (size_t)t * H);
        for (int i = threadIdx.x; i < H / 4; i += blockDim.x) {
            float4 v = src[i];
            dst[2 * i]     = __floats2half2_rn(v.x, v.y);
            dst[2 * i + 1] = __floats2half2_rn(v.z, v.w);
        }
    } else {
        const __half2 z = __floats2half2_rn(0.f, 0.f);
        for (int i = threadIdx.x; i < H / 4; i += blockDim.x) {
            dst[2 * i] = z; dst[2 * i + 1] = z;
        }
    }
}

// ---------------- FP16 mma.sync GEMM with ldmatrix ----------------
// Block 128x256x32, 8 warps (2M x 4N), warp tile 64x64 (4x8 m16n8k16).
// Smem: row pitch 80B (64B data + 16B pad) -> 8-row base offsets mod 128 are a
// permutation of the 8 x 16B bank groups => conflict-free ldmatrix phases.
#define BM 128
#define BN 256
#define BK 32
#define PITCH 80
#define STAGES 4
#define STAGE_BYTES ((BM + BN) * PITCH)          // 30720
#define GEMM_SMEM (STAGES * STAGE_BYTES)         // 122880

template<bool GELU, typename CT>
__global__ __launch_bounds__(256, 1)
void gemm_h(const __half* __restrict__ A, const __half* __restrict__ B,
            const float* __restrict__ bias, CT* __restrict__ C,
            int Ncols, int K) {
    extern __shared__ char smraw[];
    const uint32_t sbase = smem_u32(smraw);
    const int tid = threadIdx.x, lane = tid & 31, wid = tid >> 5;
    const int wm = wid & 1, wn = wid >> 1;       // 2(M) x 4(N), warp tile 64x64
    const int bm = blockIdx.y * BM, bn = blockIdx.x * BN;
    const int lr = lane >> 2, lc = lane & 3;
    const int KT = K / BK;

    float acc[4][8][4];
    #pragma unroll
    for (int i = 0; i < 4; i++)
        #pragma unroll
        for (int j = 0; j < 8; j++)
            #pragma unroll
            for (int q = 0; q < 4; q++) acc[i][j][q] = 0.f;

    // ldmatrix per-lane offsets (within a stage):
    // A x4 (one 16x16 tile): g=lane>>3: row += (g&1)*8, kbyte += (g>>1)*16
    // B x4 (two 8x16 tiles): row += (g>>1)*8, kbyte += (g&1)*16
    const int g = lane >> 3, li = lane & 7;
    const uint32_t aOff = (uint32_t)(wm * 64 + (g & 1) * 8 + li) * PITCH + ((g >> 1) << 4);
    const uint32_t bOff = (uint32_t)(wn * 64 + (g >> 1) * 8 + li) * PITCH + ((g & 1) << 4)
                        + BM * PITCH;

    const int lrow = tid >> 3;        // 0..31
    const int lch  = tid & 7;         // 8B chunk in 64B row
    auto load_stage = [&](int t, int s) {
        const int k0 = t * BK;
        const uint32_t stA = sbase + s * STAGE_BYTES;
        const uint32_t stB = stA + BM * PITCH;
        #pragma unroll
        for (int l = 0; l < 4; l++) {
            const int row = lrow + l * 32;
            cp8(stA + row * PITCH + lch * 8, A + (size_t)(bm + row) * K + k0 + lch * 4);
        }
        #pragma unroll
        for (int l = 0; l < 8; l++) {
            const int row = lrow + l * 32;
            cp8(stB + row * PITCH + lch * 8, B + (size_t)(bn + row) * K + k0 + lch * 4);
        }
    };

    #pragma unroll
    for (int t = 0; t < STAGES - 1; t++) {
        load_stage(t, t);
        asm volatile("cp.async.commit_group;" ::: "memory");
    }

    for (int t = 0; t < KT; t++) {
        asm volatile("cp.async.wait_group %0;" :: "n"(STAGES - 2) : "memory");
        __syncthreads();

        const int tn = t + STAGES - 1;
        if (tn < KT) load_stage(tn, tn % STAGES);
        asm volatile("cp.async.commit_group;" ::: "memory");

        const uint32_t stBase = sbase + (uint32_t)(t % STAGES) * STAGE_BYTES;
        const uint32_t aBase = stBase + aOff;
        const uint32_t bBase = stBase + bOff;

        #pragma unroll
        for (int ks = 0; ks < 2; ks++) {         // two k16 steps per BK=32
            uint32_t a[4][4], b[8][2];
            const uint32_t kb = ks * 32;
            #pragma unroll
            for (int mt = 0; mt < 4; mt++)
                ldsm_x4(a[mt], aBase + mt * (16 * PITCH) + kb);
            #pragma unroll
            for (int ntp = 0; ntp < 4; ntp++) {
                uint32_t r[4];
                ldsm_x4(r, bBase + ntp * (16 * PITCH) + kb);
                b[2 * ntp][0] = r[0]; b[2 * ntp][1] = r[1];
                b[2 * ntp + 1][0] = r[2]; b[2 * ntp + 1][1] = r[3];
            }
            #pragma unroll
            for (int mt = 0; mt < 4; mt++)
                #pragma unroll
                for (int nt = 0; nt < 8; nt++)
                    mma_f16(acc[mt][nt], a[mt], b[nt]);
        }
    }

    // epilogue: bias (+GELU); CT = __half (GEMM1) or float (GEMM2)
    #pragma unroll
    for (int nt = 0; nt < 8; nt++) {
        const int col = bn + wn * 64 + nt * 8 + 2 * lc;
        const float b0 = __ldg(&bias[col]), b1 = __ldg(&bias[col + 1]);
        #pragma unroll
        for (int mt = 0; mt < 4; mt++) {
            const int row0 = bm + wm * 64 + mt * 16 + lr;
            float v0 = acc[mt][nt][0] + b0;
            float v1 = acc[mt][nt][1] + b1;
            float v2 = acc[mt][nt][2] + b0;
            float v3 = acc[mt][nt][3] + b1;
            if (GELU) {
                v0 = 0.5f * v0 * (1.f + erff(v0 * 0.7071067811865475f));
                v1 = 0.5f * v1 * (1.f + erff(v1 * 0.7071067811865475f));
                v2 = 0.5f * v2 * (1.f + erff(v2 * 0.7071067811865475f));
                v3 = 0.5f * v3 * (1.f + erff(v3 * 0.7071067811865475f));
            }
            if (sizeof(CT) == 2) {
                __half2* c0 = (__half2*)((__half*)C + (size_t)row0 * Ncols + col);
                __half2* c1 = (__half2*)((__half*)C + (size_t)(row0 + 8) * Ncols + col);
                *c0 = __floats2half2_rn(v0, v1);
                *c1 = __floats2half2_rn(v2, v3);
            } else {
                *(float2*)((float*)C + (size_t)row0 * Ncols + col)       = make_float2(v0, v1);
                *(float2*)((float*)C + (size_t)(row0 + 8) * Ncols + col) = make_float2(v2, v3);
            }
        }
    }
}

// ---------------- weighted combine ----------------
__global__ void combine_kernel(int N, float* __restrict__ out) {
    const int t = blockIdx.x;
    const int d0 = g_entry_dest[t];
    const int d1 = g_entry_dest[N + t];
    const float p0 = g_entry_prob[t];
    const float p1 = g_entry_prob[N + t];
    const float4* h0 = (d0 >= 0) ? (const float4*)(g_h + (size_t)d0 * H) : nullptr;
    const float4* h1 = (d1 >= 0) ? (const float4*)(g_h + (size_t)d1 * H) : nullptr;
    float4* o = (float4*)(out + (size_t)t * H);
    for (int i = threadIdx.x; i < H / 4; i += blockDim.x) {
        float4 acc = make_float4(0.f, 0.f, 0.f, 0.f);
        if (h0) { float4 v = h0[i]; acc.x += p0*v.x; acc.y += p0*v.y; acc.z += p0*v.z; acc.w += p0*v.w; }
        if (h1) { float4 v = h1[i]; acc.x += p1*v.x; acc.y += p1*v.y; acc.z += p1*v.z; acc.w += p1*v.w; }
        o[i] = acc;
    }
}

// ---------------- launch ----------------
extern "C" void kernel_launch(void* const* d_in, const int* in_sizes, int n_in,
                              void* d_out, int out_size) {
    const float* x  = (const float*)d_in[0];
    const float* rw = (const float*)d_in[1];
    const float* w1 = (const float*)d_in[2];
    const float* b1 = (const float*)d_in[3];
    const float* w2 = (const float*)d_in[4];
    const float* b2 = (const float*)d_in[5];
    float* out = (float*)d_out;

    const int N = in_sizes[0] / H;   // 2048

    __half* bufh; cudaGetSymbolAddress((void**)&bufh, g_bufh);
    __half* acth; cudaGetSymbolAddress((void**)&acth, g_acth);
    __half* w1h;  cudaGetSymbolAddress((void**)&w1h, g_w1h);
    __half* w2h;  cudaGetSymbolAddress((void**)&w2h, g_w2h);
    float*  hbf;  cudaGetSymbolAddress((void**)&hbf, g_h);

    cudaFuncSetAttribute(gemm_h<true, __half>,
                         cudaFuncAttributeMaxDynamicSharedMemorySize, GEMM_SMEM);
    cudaFuncSetAttribute(gemm_h<false, float>,
                         cudaFuncAttributeMaxDynamicSharedMemorySize, GEMM_SMEM);

    {   // weight fp16 conversion
        size_t n4 = (size_t)F * H / 4;
        tohalf<<<(unsigned)((n4 + 255) / 256), 256>>>(w1, w1h, n4);
        tohalf<<<(unsigned)((n4 + 255) / 256), 256>>>(w2, w2h, n4);
    }

    router_kernel<<<N, 256>>>(x, rw, N);
    assign_kernel<<<1, 256>>>(N);
    dispatch_kernel<<<NSLOT, 256>>>(x);

    // GEMM1: buf[4096,2048] @ w1h^T -> gelu -> act (fp16)
    gemm_h<true, __half><<<dim3(F / BN, NSLOT / BM), 256, GEMM_SMEM>>>(
        bufh, w1h, b1, acth, F, H);
    // GEMM2: act[4096,8192] @ w2h^T + b2 -> h (fp32)
    gemm_h<false, float><<<dim3(H / BN, NSLOT / BM), 256, GEMM_SMEM>>>(
        acth, w2h, b2, hbf, H, F);

    combine_kernel<<<N, 256>>>(N, out);
}

// round 9
// speedup vs baseline: 7.4255x; 1.1529x over previous
#include <cuda_runtime.h>
#include <cuda_fp16.h>
#include <cstdint>
#include <math.h>

#define E 8
#define TOPK 2
#define CAP 512
#define H 2048
#define F 8192
#define NSLOT (E*CAP)   // 4096

// ---------------- scratch (no allocation allowed) ----------------
__device__ __half g_bufh[(size_t)NSLOT * H];  // dispatch buffer fp16
__device__ __half g_acth[(size_t)NSLOT * F];  // gelu acts fp16
__device__ __half g_w1h[(size_t)F * H];       // w1 fp16
__device__ __half g_w2h[(size_t)H * F];       // w2 fp16
__device__ float  g_h[(size_t)NSLOT * H];     // expert output fp32
__device__ int    g_entry_expert[2 * 2048];
__device__ float  g_entry_prob  [2 * 2048];
__device__ int    g_entry_dest  [2 * 2048];
__device__ int    g_slot_token  [NSLOT];

// ---------------- helpers ----------------
__device__ __forceinline__ uint32_t smem_u32(const void* p) {
    uint32_t a;
    asm("{ .reg .u64 t; cvta.to.shared.u64 t, %1; cvt.u32.u64 %0, t; }"
        : "=r"(a) : "l"(p));
    return a;
}
__device__ __forceinline__ void cp16(uint32_t dst, const void* src) {
    asm volatile("cp.async.cg.shared.global [%0], [%1], 16;"
                 :: "r"(dst), "l"(src) : "memory");
}
__device__ __forceinline__ void ldsm_x4(uint32_t* r, uint32_t addr) {
    asm volatile("ldmatrix.sync.aligned.m8n8.x4.shared.b16 {%0,%1,%2,%3}, [%4];"
                 : "=r"(r[0]), "=r"(r[1]), "=r"(r[2]), "=r"(r[3]) : "r"(addr));
}
__device__ __forceinline__ void mma_f16(float* c, const uint32_t* a, const uint32_t* b) {
    asm volatile(
        "mma.sync.aligned.m16n8k16.row.col.f32.f16.f16.f32 "
        "{%0,%1,%2,%3}, {%4,%5,%6,%7}, {%8,%9}, {%0,%1,%2,%3};"
        : "+f"(c[0]), "+f"(c[1]), "+f"(c[2]), "+f"(c[3])
        : "r"(a[0]), "r"(a[1]), "r"(a[2]), "r"(a[3]), "r"(b[0]), "r"(b[1]));
}

// ---------------- fp32 -> fp16 conversion pass (weights) ----------------
__global__ void tohalf(const float* __restrict__ src, __half* __restrict__ dst,
                       size_t n4) {
    size_t i = (size_t)blockIdx.x * blockDim.x + threadIdx.x;
    if (i < n4) {
        float4 v = ((const float4*)src)[i];
        ((__half2*)dst)[2 * i]     = __floats2half2_rn(v.x, v.y);
        ((__half2*)dst)[2 * i + 1] = __floats2half2_rn(v.z, v.w);
    }
}

// ---------------- router ----------------
__global__ void router_kernel(const float* __restrict__ x,
                              const float* __restrict__ rw, int N) {
    const int t = blockIdx.x;
    const int tid = threadIdx.x;
    const int lane = tid & 31, warp = tid >> 5;

    __shared__ float xs[H];
    const float4* xv = (const float4*)(x + (size_t)t * H);
    float4* xsv = (float4*)xs;
    for (int i = tid; i < H / 4; i += 256) xsv[i] = xv[i];
    __syncthreads();

    const float* wr = rw + (size_t)warp * H;
    float s = 0.f;
    for (int i = lane; i < H; i += 32) s += xs[i] * wr[i];
    #pragma unroll
    for (int o = 16; o; o >>= 1) s += __shfl_xor_sync(0xffffffffu, s, o);

    __shared__ float logits[E];
    if (lane == 0) logits[warp] = s;
    __syncthreads();

    if (tid == 0) {
        float m = logits[0];
        #pragma unroll
        for (int e = 1; e < E; e++) m = fmaxf(m, logits[e]);
        float p[E], den = 0.f;
        #pragma unroll
        for (int e = 0; e < E; e++) { p[e] = __expf(logits[e] - m); den += p[e]; }
        float inv = 1.f / den;
        #pragma unroll
        for (int e = 0; e < E; e++) p[e] *= inv;
        int i0 = 0;
        #pragma unroll
        for (int e = 1; e < E; e++) if (p[e] > p[i0]) i0 = e;
        int i1 = (i0 == 0) ? 1 : 0;
        #pragma unroll
        for (int e = 0; e < E; e++) if (e != i0 && p[e] > p[i1]) i1 = e;
        g_entry_expert[t]     = i0; g_entry_prob[t]     = p[i0];
        g_entry_expert[N + t] = i1; g_entry_prob[N + t] = p[i1];
    }
}

// ---------------- capacity scan: warp-per-expert ballot rank ----------------
__global__ void assign_kernel(int N) {
    const int NK = TOPK * N;                    // 4096
    const int tid = threadIdx.x;
    const int lane = tid & 31, warp = tid >> 5;

    __shared__ int se[2 * 2048];
    for (int i = tid; i < NSLOT; i += blockDim.x) g_slot_token[i] = -1;
    for (int i = tid; i < NK; i += blockDim.x) se[i] = g_entry_expert[i];
    __syncthreads();

    if (warp < E) {
        const int e = warp;
        const unsigned lt = (1u << lane) - 1u;
        int cnt = 0;
        for (int base = 0; base < NK; base += 32) {
            const int idx = base + lane;
            const bool match = (idx < NK) && (se[idx] == e);
            const unsigned m = __ballot_sync(0xffffffffu, match);
            if (match) {
                const int pos = cnt + __popc(m & lt);
                if (pos < CAP) {
                    const int d = e * CAP + pos;
                    g_entry_dest[idx] = d;
                    g_slot_token[d] = idx % N;
                } else {
                    g_entry_dest[idx] = -1;
                }
            }
            cnt += __popc(m);
        }
    }
}

// ---------------- gather tokens (fp16) into dispatch buffer ----------------
__global__ void dispatch_kernel(const float* __restrict__ x) {
    const int slot = blockIdx.x;
    const int t = g_slot_token[slot];
    __half2* dst = (__half2*)(g_bufh + (size_t)slot * H);
    if (t >= 0) {
        const float4* src = (const float4*)(x + (size_t)t * H);
        for (int i = threadIdx.x; i < H / 4; i += blockDim.x) {
            float4 v = src[i];
            dst[2 * i]     = __floats2half2_rn(v.x, v.y);
            dst[2 * i + 1] = __floats2half2_rn(v.z, v.w);
        }
    } else {
        const __half2 z = __floats2half2_rn(0.f, 0.f);
        for (int i = threadIdx.x; i < H / 4; i += blockDim.x) {
            dst[2 * i] = z; dst[2 * i + 1] = z;
        }
    }
}

// ---------------- FP16 mma.sync GEMM with ldmatrix, BK=64 ----------------
// Block 128x256x64, 8 warps (2M x 4N), warp tile 64x64 (4x8 m16n8k16).
// Smem: row = 128B data + 16B pad (pitch 144). 144 mod 128 = 16 -> 8
// consecutive rows' bases are a permutation of the 8 x 16B bank groups =>
// conflict-free ldmatrix phases. 3-stage cp.async (16B) pipeline.
#define BM 128
#define BN 256
#define BK 64
#define PITCH 144
#define STAGES 3
#define STAGE_BYTES ((BM + BN) * PITCH)          // 55296
#define GEMM_SMEM (STAGES * STAGE_BYTES)         // 165888

template<bool GELU, typename CT>
__global__ __launch_bounds__(256, 1)
void gemm_h(const __half* __restrict__ A, const __half* __restrict__ B,
            const float* __restrict__ bias, CT* __restrict__ C,
            int Ncols, int K) {
    extern __shared__ char smraw[];
    const uint32_t sbase = smem_u32(smraw);
    const int tid = threadIdx.x, lane = tid & 31, wid = tid >> 5;
    const int wm = wid & 1, wn = wid >> 1;       // 2(M) x 4(N), warp tile 64x64
    const int bm = blockIdx.y * BM, bn = blockIdx.x * BN;
    const int lr = lane >> 2, lc = lane & 3;
    const int KT = K / BK;

    float acc[4][8][4];
    #pragma unroll
    for (int i = 0; i < 4; i++)
        #pragma unroll
        for (int j = 0; j < 8; j++)
            #pragma unroll
            for (int q = 0; q < 4; q++) acc[i][j][q] = 0.f;

    // ldmatrix per-lane offsets (within a stage):
    // A x4 (one 16x16 tile): g=lane>>3: row += (g&1)*8, kbyte += (g>>1)*16
    // B x4 (two 8x16 tiles): row += (g>>1)*8, kbyte += (g&1)*16
    const int g = lane >> 3, li = lane & 7;
    const uint32_t aOff = (uint32_t)(wm * 64 + (g & 1) * 8 + li) * PITCH + ((g >> 1) << 4);
    const uint32_t bOff = (uint32_t)(wn * 64 + (g >> 1) * 8 + li) * PITCH + ((g & 1) << 4)
                        + BM * PITCH;

    const int lrow = tid >> 3;        // 0..31
    const int lch  = tid & 7;         // 16B chunk in 128B row
    auto load_stage = [&](int t, int s) {
        const int k0 = t * BK;
        const uint32_t stA = sbase + s * STAGE_BYTES;
        const uint32_t stB = stA + BM * PITCH;
        #pragma unroll
        for (int l = 0; l < 4; l++) {
            const int row = lrow + l * 32;
            cp16(stA + row * PITCH + lch * 16, A + (size_t)(bm + row) * K + k0 + lch * 8);
        }
        #pragma unroll
        for (int l = 0; l < 8; l++) {
            const int row = lrow + l * 32;
            cp16(stB + row * PITCH + lch * 16, B + (size_t)(bn + row) * K + k0 + lch * 8);
        }
    };

    #pragma unroll
    for (int t = 0; t < STAGES - 1; t++) {
        load_stage(t, t);
        asm volatile("cp.async.commit_group;" ::: "memory");
    }

    for (int t = 0; t < KT; t++) {
        asm volatile("cp.async.wait_group %0;" :: "n"(STAGES - 2) : "memory");
        __syncthreads();

        const int tn = t + STAGES - 1;
        if (tn < KT) load_stage(tn, tn % STAGES);
        asm volatile("cp.async.commit_group;" ::: "memory");

        const uint32_t stBase = sbase + (uint32_t)(t % STAGES) * STAGE_BYTES;
        const uint32_t aBase = stBase + aOff;
        const uint32_t bBase = stBase + bOff;

        #pragma unroll
        for (int ks = 0; ks < 4; ks++) {         // four k16 steps per BK=64
            uint32_t a[4][4], b[8][2];
            const uint32_t kb = ks * 32;
            #pragma unroll
            for (int mt = 0; mt < 4; mt++)
                ldsm_x4(a[mt], aBase + mt * (16 * PITCH) + kb);
            #pragma unroll
            for (int ntp = 0; ntp < 4; ntp++) {
                uint32_t r[4];
                ldsm_x4(r, bBase + ntp * (16 * PITCH) + kb);
                b[2 * ntp][0] = r[0]; b[2 * ntp][1] = r[1];
                b[2 * ntp + 1][0] = r[2]; b[2 * ntp + 1][1] = r[3];
            }
            #pragma unroll
            for (int mt = 0; mt < 4; mt++)
                #pragma unroll
                for (int nt = 0; nt < 8; nt++)
                    mma_f16(acc[mt][nt], a[mt], b[nt]);
        }
    }

    // epilogue: bias (+GELU); CT = __half (GEMM1) or float (GEMM2)
    #pragma unroll
    for (int nt = 0; nt < 8; nt++) {
        const int col = bn + wn * 64 + nt * 8 + 2 * lc;
        const float b0 = __ldg(&bias[col]), b1 = __ldg(&bias[col + 1]);
        #pragma unroll
        for (int mt = 0; mt < 4; mt++) {
            const int row0 = bm + wm * 64 + mt * 16 + lr;
            float v0 = acc[mt][nt][0] + b0;
            float v1 = acc[mt][nt][1] + b1;
            float v2 = acc[mt][nt][2] + b0;
            float v3 = acc[mt][nt][3] + b1;
            if (GELU) {
                v0 = 0.5f * v0 * (1.f + erff(v0 * 0.7071067811865475f));
                v1 = 0.5f * v1 * (1.f + erff(v1 * 0.7071067811865475f));
                v2 = 0.5f * v2 * (1.f + erff(v2 * 0.7071067811865475f));
                v3 = 0.5f * v3 * (1.f + erff(v3 * 0.7071067811865475f));
            }
            if (sizeof(CT) == 2) {
                __half2* c0 = (__half2*)((__half*)C + (size_t)row0 * Ncols + col);
                __half2* c1 = (__half2*)((__half*)C + (size_t)(row0 + 8) * Ncols + col);
                *c0 = __floats2half2_rn(v0, v1);
                *c1 = __floats2half2_rn(v2, v3);
            } else {
                *(float2*)((float*)C + (size_t)row0 * Ncols + col)       = make_float2(v0, v1);
                *(float2*)((float*)C + (size_t)(row0 + 8) * Ncols + col) = make_float2(v2, v3);
            }
        }
    }
}

// ---------------- weighted combine ----------------
__global__ void combine_kernel(int N, float* __restrict__ out) {
    const int t = blockIdx.x;
    const int d0 = g_entry_dest[t];
    const int d1 = g_entry_dest[N + t];
    const float p0 = g_entry_prob[t];
    const float p1 = g_entry_prob[N + t];
    const float4* h0 = (d0 >= 0) ? (const float4*)(g_h + (size_t)d0 * H) : nullptr;
    const float4* h1 = (d1 >= 0) ? (const float4*)(g_h + (size_t)d1 * H) : nullptr;
    float4* o = (float4*)(out + (size_t)t * H);
    for (int i = threadIdx.x; i < H / 4; i += blockDim.x) {
        float4 acc = make_float4(0.f, 0.f, 0.f, 0.f);
        if (h0) { float4 v = h0[i]; acc.x += p0*v.x; acc.y += p0*v.y; acc.z += p0*v.z; acc.w += p0*v.w; }
        if (h1) { float4 v = h1[i]; acc.x += p1*v.x; acc.y += p1*v.y; acc.z += p1*v.z; acc.w += p1*v.w; }
        o[i] = acc;
    }
}

// ---------------- launch ----------------
extern "C" void kernel_launch(void* const* d_in, const int* in_sizes, int n_in,
                              void* d_out, int out_size) {
    const float* x  = (const float*)d_in[0];
    const float* rw = (const float*)d_in[1];
    const float* w1 = (const float*)d_in[2];
    const float* b1 = (const float*)d_in[3];
    const float* w2 = (const float*)d_in[4];
    const float* b2 = (const float*)d_in[5];
    float* out = (float*)d_out;

    const int N = in_sizes[0] / H;   // 2048

    __half* bufh; cudaGetSymbolAddress((void**)&bufh, g_bufh);
    __half* acth; cudaGetSymbolAddress((void**)&acth, g_acth);
    __half* w1h;  cudaGetSymbolAddress((void**)&w1h, g_w1h);
    __half* w2h;  cudaGetSymbolAddress((void**)&w2h, g_w2h);
    float*  hbf;  cudaGetSymbolAddress((void**)&hbf, g_h);

    cudaFuncSetAttribute(gemm_h<true, __half>,
                         cudaFuncAttributeMaxDynamicSharedMemorySize, GEMM_SMEM);
    cudaFuncSetAttribute(gemm_h<false, float>,
                         cudaFuncAttributeMaxDynamicSharedMemorySize, GEMM_SMEM);

    {   // weight fp16 conversion
        size_t n4 = (size_t)F * H / 4;
        tohalf<<<(unsigned)((n4 + 255) / 256), 256>>>(w1, w1h, n4);
        tohalf<<<(unsigned)((n4 + 255) / 256), 256>>>(w2, w2h, n4);
    }

    router_kernel<<<N, 256>>>(x, rw, N);
    assign_kernel<<<1, 256>>>(N);
    dispatch_kernel<<<NSLOT, 256>>>(x);

    // GEMM1: buf[4096,2048] @ w1h^T -> gelu -> act (fp16)
    gemm_h<true, __half><<<dim3(F / BN, NSLOT / BM), 256, GEMM_SMEM>>>(
        bufh, w1h, b1, acth, F, H);
    // GEMM2: act[4096,8192] @ w2h^T + b2 -> h (fp32)
    gemm_h<false, float><<<dim3(H / BN, NSLOT / BM), 256, GEMM_SMEM>>>(
        acth, w2h, b2, hbf, H, F);

    combine_kernel<<<N, 256>>>(N, out);
}

// round 10
// speedup vs baseline: 7.4381x; 1.0017x over previous
#include <cuda_runtime.h>
#include <cuda_fp16.h>
#include <cstdint>
#include <math.h>

#define E 8
#define TOPK 2
#define CAP 512
#define H 2048
#define F 8192
#define NSLOT (E*CAP)   // 4096

// ---------------- scratch (no allocation allowed) ----------------
__device__ __half g_bufh[(size_t)NSLOT * H];  // dispatch buffer fp16
__device__ __half g_acth[(size_t)NSLOT * F];  // gelu acts fp16
__device__ __half g_w1h[(size_t)F * H];       // w1 fp16
__device__ __half g_w2h[(size_t)H * F];       // w2 fp16
__device__ float  g_h[(size_t)NSLOT * H];     // expert output fp32
__device__ int    g_entry_expert[2 * 2048];
__device__ float  g_entry_prob  [2 * 2048];
__device__ int    g_entry_dest  [2 * 2048];
__device__ int    g_slot_token  [NSLOT];

// ---------------- helpers ----------------
__device__ __forceinline__ uint32_t smem_u32(const void* p) {
    uint32_t a;
    asm("{ .reg .u64 t; cvta.to.shared.u64 t, %1; cvt.u32.u64 %0, t; }"
        : "=r"(a) : "l"(p));
    return a;
}
__device__ __forceinline__ void cp16(uint32_t dst, const void* src) {
    asm volatile("cp.async.cg.shared.global [%0], [%1], 16;"
                 :: "r"(dst), "l"(src) : "memory");
}
__device__ __forceinline__ void ldsm_x4(uint32_t* r, uint32_t addr) {
    asm volatile("ldmatrix.sync.aligned.m8n8.x4.shared.b16 {%0,%1,%2,%3}, [%4];"
                 : "=r"(r[0]), "=r"(r[1]), "=r"(r[2]), "=r"(r[3]) : "r"(addr));
}
__device__ __forceinline__ void mma_f16(float* c, const uint32_t* a, const uint32_t* b) {
    asm volatile(
        "mma.sync.aligned.m16n8k16.row.col.f32.f16.f16.f32 "
        "{%0,%1,%2,%3}, {%4,%5,%6,%7}, {%8,%9}, {%0,%1,%2,%3};"
        : "+f"(c[0]), "+f"(c[1]), "+f"(c[2]), "+f"(c[3])
        : "r"(a[0]), "r"(a[1]), "r"(a[2]), "r"(a[3]), "r"(b[0]), "r"(b[1]));
}

// ---------------- fp32 -> fp16 conversion pass (weights) ----------------
__global__ void tohalf(const float* __restrict__ src, __half* __restrict__ dst,
                       size_t n4) {
    size_t i = (size_t)blockIdx.x * blockDim.x + threadIdx.x;
    if (i < n4) {
        float4 v = ((const float4*)src)[i];
        ((__half2*)dst)[2 * i]     = __floats2half2_rn(v.x, v.y);
        ((__half2*)dst)[2 * i + 1] = __floats2half2_rn(v.z, v.w);
    }
}

// ---------------- router ----------------
__global__ void router_kernel(const float* __restrict__ x,
                              const float* __restrict__ rw, int N) {
    const int t = blockIdx.x;
    const int tid = threadIdx.x;
    const int lane = tid & 31, warp = tid >> 5;

    __shared__ float xs[H];
    const float4* xv = (const float4*)(x + (size_t)t * H);
    float4* xsv = (float4*)xs;
    for (int i = tid; i < H / 4; i += 256) xsv[i] = xv[i];
    __syncthreads();

    const float* wr = rw + (size_t)warp * H;
    float s = 0.f;
    for (int i = lane; i < H; i += 32) s += xs[i] * wr[i];
    #pragma unroll
    for (int o = 16; o; o >>= 1) s += __shfl_xor_sync(0xffffffffu, s, o);

    __shared__ float logits[E];
    if (lane == 0) logits[warp] = s;
    __syncthreads();

    if (tid == 0) {
        float m = logits[0];
        #pragma unroll
        for (int e = 1; e < E; e++) m = fmaxf(m, logits[e]);
        float p[E], den = 0.f;
        #pragma unroll
        for (int e = 0; e < E; e++) { p[e] = __expf(logits[e] - m); den += p[e]; }
        float inv = 1.f / den;
        #pragma unroll
        for (int e = 0; e < E; e++) p[e] *= inv;
        int i0 = 0;
        #pragma unroll
        for (int e = 1; e < E; e++) if (p[e] > p[i0]) i0 = e;
        int i1 = (i0 == 0) ? 1 : 0;
        #pragma unroll
        for (int e = 0; e < E; e++) if (e != i0 && p[e] > p[i1]) i1 = e;
        g_entry_expert[t]     = i0; g_entry_prob[t]     = p[i0];
        g_entry_expert[N + t] = i1; g_entry_prob[N + t] = p[i1];
    }
}

// ---------------- capacity scan: warp-per-expert ballot rank ----------------
__global__ void assign_kernel(int N) {
    const int NK = TOPK * N;                    // 4096
    const int tid = threadIdx.x;
    const int lane = tid & 31, warp = tid >> 5;

    __shared__ int se[2 * 2048];
    for (int i = tid; i < NSLOT; i += blockDim.x) g_slot_token[i] = -1;
    for (int i = tid; i < NK; i += blockDim.x) se[i] = g_entry_expert[i];
    __syncthreads();

    if (warp < E) {
        const int e = warp;
        const unsigned lt = (1u << lane) - 1u;
        int cnt = 0;
        for (int base = 0; base < NK; base += 32) {
            const int idx = base + lane;
            const bool match = (idx < NK) && (se[idx] == e);
            const unsigned m = __ballot_sync(0xffffffffu, match);
            if (match) {
                const int pos = cnt + __popc(m & lt);
                if (pos < CAP) {
                    const int d = e * CAP + pos;
                    g_entry_dest[idx] = d;
                    g_slot_token[d] = idx % N;
                } else {
                    g_entry_dest[idx] = -1;
                }
            }
            cnt += __popc(m);
        }
    }
}

// ---------------- gather tokens (fp16) into dispatch buffer ----------------
__global__ void dispatch_kernel(const float* __restrict__ x) {
    const int slot = blockIdx.x;
    const int t = g_slot_token[slot];
    __half2* dst = (__half2*)(g_bufh + (size_t)slot * H);
    if (t >= 0) {
        const float4* src = (const float4*)(x + (size_t)t * H);
        for (int i = threadIdx.x; i < H / 4; i += blockDim.x) {
            float4 v = src[i];
            dst[2 * i]     = __floats2half2_rn(v.x, v.y);
            dst[2 * i + 1] = __floats2half2_rn(v.z, v.w);
        }
    } else {
        const __half2 z = __floats2half2_rn(0.f, 0.f);
        for (int i = threadIdx.x; i < H / 4; i += blockDim.x) {
            dst[2 * i] = z; dst[2 * i + 1] = z;
        }
    }
}

// ---------------- FP16 mma.sync GEMM, ldmatrix + fragment double-buffer ----------------
// Block 128x256x64, 8 warps (2M x 4N), warp tile 64x64 (4x8 m16n8k16).
// Smem pitch 144 (128B data + 16B pad): conflict-free ldmatrix phases.
// 3-stage cp.async pipeline across tiles; fragment double-buffer within a tile.
#define BM 128
#define BN 256
#define BK 64
#define PITCH 144
#define STAGES 3
#define STAGE_BYTES ((BM + BN) * PITCH)          // 55296
#define GEMM_SMEM (STAGES * STAGE_BYTES)         // 165888

template<bool GELU, typename CT>
__global__ __launch_bounds__(256, 1)
void gemm_h(const __half* __restrict__ A, const __half* __restrict__ B,
            const float* __restrict__ bias, CT* __restrict__ C,
            int Ncols, int K) {
    extern __shared__ char smraw[];
    const uint32_t sbase = smem_u32(smraw);
    const int tid = threadIdx.x, lane = tid & 31, wid = tid >> 5;
    const int wm = wid & 1, wn = wid >> 1;       // 2(M) x 4(N), warp tile 64x64
    const int bm = blockIdx.y * BM, bn = blockIdx.x * BN;
    const int lr = lane >> 2, lc = lane & 3;
    const int KT = K / BK;

    float acc[4][8][4];
    #pragma unroll
    for (int i = 0; i < 4; i++)
        #pragma unroll
        for (int j = 0; j < 8; j++)
            #pragma unroll
            for (int q = 0; q < 4; q++) acc[i][j][q] = 0.f;

    const int g = lane >> 3, li = lane & 7;
    const uint32_t aOff = (uint32_t)(wm * 64 + (g & 1) * 8 + li) * PITCH + ((g >> 1) << 4);
    const uint32_t bOff = (uint32_t)(wn * 64 + (g >> 1) * 8 + li) * PITCH + ((g & 1) << 4)
                        + BM * PITCH;

    const int lrow = tid >> 3;        // 0..31
    const int lch  = tid & 7;         // 16B chunk in 128B row
    auto load_stage = [&](int t, int s) {
        const int k0 = t * BK;
        const uint32_t stA = sbase + s * STAGE_BYTES;
        const uint32_t stB = stA + BM * PITCH;
        #pragma unroll
        for (int l = 0; l < 4; l++) {
            const int row = lrow + l * 32;
            cp16(stA + row * PITCH + lch * 16, A + (size_t)(bm + row) * K + k0 + lch * 8);
        }
        #pragma unroll
        for (int l = 0; l < 8; l++) {
            const int row = lrow + l * 32;
            cp16(stB + row * PITCH + lch * 16, B + (size_t)(bn + row) * K + k0 + lch * 8);
        }
    };

    #pragma unroll
    for (int t = 0; t < STAGES - 1; t++) {
        load_stage(t, t);
        asm volatile("cp.async.commit_group;" ::: "memory");
    }

    uint32_t a[2][4][4], b[2][8][2];

    for (int t = 0; t < KT; t++) {
        asm volatile("cp.async.wait_group %0;" :: "n"(STAGES - 2) : "memory");
        __syncthreads();

        const int tn = t + STAGES - 1;
        if (tn < KT) load_stage(tn, tn % STAGES);
        asm volatile("cp.async.commit_group;" ::: "memory");

        const uint32_t stBase = sbase + (uint32_t)(t % STAGES) * STAGE_BYTES;
        const uint32_t aBase = stBase + aOff;
        const uint32_t bBase = stBase + bOff;

        auto load_frags = [&](int buf, int ks) {
            const uint32_t kb = (uint32_t)ks * 32;
            #pragma unroll
            for (int mt = 0; mt < 4; mt++)
                ldsm_x4(a[buf][mt], aBase + mt * (16 * PITCH) + kb);
            #pragma unroll
            for (int ntp = 0; ntp < 4; ntp++) {
                uint32_t r[4];
                ldsm_x4(r, bBase + ntp * (16 * PITCH) + kb);
                b[buf][2 * ntp][0] = r[0]; b[buf][2 * ntp][1] = r[1];
                b[buf][2 * ntp + 1][0] = r[2]; b[buf][2 * ntp + 1][1] = r[3];
            }
        };

        load_frags(0, 0);
        #pragma unroll
        for (int ks = 0; ks < 4; ks++) {         // four k16 steps per BK=64
            const int cur = ks & 1;
            if (ks < 3) load_frags(cur ^ 1, ks + 1);
            #pragma unroll
            for (int mt = 0; mt < 4; mt++)
                #pragma unroll
                for (int nt = 0; nt < 8; nt++)
                    mma_f16(acc[mt][nt], a[cur][mt], b[cur][nt]);
        }
    }

    // epilogue: bias (+GELU); CT = __half (GEMM1) or float (GEMM2)
    #pragma unroll
    for (int nt = 0; nt < 8; nt++) {
        const int col = bn + wn * 64 + nt * 8 + 2 * lc;
        const float b0 = __ldg(&bias[col]), b1 = __ldg(&bias[col + 1]);
        #pragma unroll
        for (int mt = 0; mt < 4; mt++) {
            const int row0 = bm + wm * 64 + mt * 16 + lr;
            float v0 = acc[mt][nt][0] + b0;
            float v1 = acc[mt][nt][1] + b1;
            float v2 = acc[mt][nt][2] + b0;
            float v3 = acc[mt][nt][3] + b1;
            if (GELU) {
                v0 = 0.5f * v0 * (1.f + erff(v0 * 0.7071067811865475f));
                v1 = 0.5f * v1 * (1.f + erff(v1 * 0.7071067811865475f));
                v2 = 0.5f * v2 * (1.f + erff(v2 * 0.7071067811865475f));
                v3 = 0.5f * v3 * (1.f + erff(v3 * 0.7071067811865475f));
            }
            if (sizeof(CT) == 2) {
                __half2* c0 = (__half2*)((__half*)C + (size_t)row0 * Ncols + col);
                __half2* c1 = (__half2*)((__half*)C + (size_t)(row0 + 8) * Ncols + col);
                *c0 = __floats2half2_rn(v0, v1);
                *c1 = __floats2half2_rn(v2, v3);
            } else {
                *(float2*)((float*)C + (size_t)row0 * Ncols + col)       = make_float2(v0, v1);
                *(float2*)((float*)C + (size_t)(row0 + 8) * Ncols + col) = make_float2(v2, v3);
            }
        }
    }
}

// ---------------- weighted combine ----------------
__global__ void combine_kernel(int N, float* __restrict__ out) {
    const int t = blockIdx.x;
    const int d0 = g_entry_dest[t];
    const int d1 = g_entry_dest[N + t];
    const float p0 = g_entry_prob[t];
    const float p1 = g_entry_prob[N + t];
    const float4* h0 = (d0 >= 0) ? (const float4*)(g_h + (size_t)d0 * H) : nullptr;
    const float4* h1 = (d1 >= 0) ? (const float4*)(g_h + (size_t)d1 * H) : nullptr;
    float4* o = (float4*)(out + (size_t)t * H);
    for (int i = threadIdx.x; i < H / 4; i += blockDim.x) {
        float4 acc = make_float4(0.f, 0.f, 0.f, 0.f);
        if (h0) { float4 v = h0[i]; acc.x += p0*v.x; acc.y += p0*v.y; acc.z += p0*v.z; acc.w += p0*v.w; }
        if (h1) { float4 v = h1[i]; acc.x += p1*v.x; acc.y += p1*v.y; acc.z += p1*v.z; acc.w += p1*v.w; }
        o[i] = acc;
    }
}

// ---------------- launch ----------------
extern "C" void kernel_launch(void* const* d_in, const int* in_sizes, int n_in,
                              void* d_out, int out_size) {
    const float* x  = (const float*)d_in[0];
    const float* rw = (const float*)d_in[1];
    const float* w1 = (const float*)d_in[2];
    const float* b1 = (const float*)d_in[3];
    const float* w2 = (const float*)d_in[4];
    const float* b2 = (const float*)d_in[5];
    float* out = (float*)d_out;

    const int N = in_sizes[0] / H;   // 2048

    __half* bufh; cudaGetSymbolAddress((void**)&bufh, g_bufh);
    __half* acth; cudaGetSymbolAddress((void**)&acth, g_acth);
    __half* w1h;  cudaGetSymbolAddress((void**)&w1h, g_w1h);
    __half* w2h;  cudaGetSymbolAddress((void**)&w2h, g_w2h);
    float*  hbf;  cudaGetSymbolAddress((void**)&hbf, g_h);

    cudaFuncSetAttribute(gemm_h<true, __half>,
                         cudaFuncAttributeMaxDynamicSharedMemorySize, GEMM_SMEM);
    cudaFuncSetAttribute(gemm_h<false, float>,
                         cudaFuncAttributeMaxDynamicSharedMemorySize, GEMM_SMEM);

    {   // weight fp16 conversion
        size_t n4 = (size_t)F * H / 4;
        tohalf<<<(unsigned)((n4 + 255) / 256), 256>>>(w1, w1h, n4);
        tohalf<<<(unsigned)((n4 + 255) / 256), 256>>>(w2, w2h, n4);
    }

    router_kernel<<<N, 256>>>(x, rw, N);
    assign_kernel<<<1, 256>>>(N);
    dispatch_kernel<<<NSLOT, 256>>>(x);

    // GEMM1: buf[4096,2048] @ w1h^T -> gelu -> act (fp16)
    gemm_h<true, __half><<<dim3(F / BN, NSLOT / BM), 256, GEMM_SMEM>>>(
        bufh, w1h, b1, acth, F, H);
    // GEMM2: act[4096,8192] @ w2h^T + b2 -> h (fp32)
    gemm_h<false, float><<<dim3(H / BN, NSLOT / BM), 256, GEMM_SMEM>>>(
        acth, w2h, b2, hbf, H, F);

    combine_kernel<<<N, 256>>>(N, out);
}

// round 11
// speedup vs baseline: 7.8083x; 1.0498x over previous
#include <cuda_runtime.h>
#include <cuda_fp16.h>
#include <cstdint>
#include <math.h>

#define E 8
#define TOPK 2
#define CAP 512
#define H 2048
#define F 8192
#define NSLOT (E*CAP)   // 4096

// ---------------- scratch (no allocation allowed) ----------------
__device__ __half g_bufh[(size_t)NSLOT * H];  // dispatch buffer fp16
__device__ __half g_acth[(size_t)NSLOT * F];  // gelu acts fp16
__device__ __half g_w1h[(size_t)F * H];       // w1 fp16
__device__ __half g_w2h[(size_t)H * F];       // w2 fp16
__device__ float  g_h[(size_t)NSLOT * H];     // expert output fp32
__device__ int    g_entry_expert[2 * 2048];
__device__ float  g_entry_prob  [2 * 2048];
__device__ int    g_entry_dest  [2 * 2048];
__device__ int    g_slot_token  [NSLOT];

// ---------------- helpers ----------------
__device__ __forceinline__ uint32_t smem_u32(const void* p) {
    uint32_t a;
    asm("{ .reg .u64 t; cvta.to.shared.u64 t, %1; cvt.u32.u64 %0, t; }"
        : "=r"(a) : "l"(p));
    return a;
}
__device__ __forceinline__ void cp16(uint32_t dst, const void* src) {
    asm volatile("cp.async.cg.shared.global [%0], [%1], 16;"
                 :: "r"(dst), "l"(src) : "memory");
}
__device__ __forceinline__ void ldsm_x4(uint32_t* r, uint32_t addr) {
    asm volatile("ldmatrix.sync.aligned.m8n8.x4.shared.b16 {%0,%1,%2,%3}, [%4];"
                 : "=r"(r[0]), "=r"(r[1]), "=r"(r[2]), "=r"(r[3]) : "r"(addr));
}
__device__ __forceinline__ void mma_f16(float* c, const uint32_t* a, const uint32_t* b) {
    asm volatile(
        "mma.sync.aligned.m16n8k16.row.col.f32.f16.f16.f32 "
        "{%0,%1,%2,%3}, {%4,%5,%6,%7}, {%8,%9}, {%0,%1,%2,%3};"
        : "+f"(c[0]), "+f"(c[1]), "+f"(c[2]), "+f"(c[3])
        : "r"(a[0]), "r"(a[1]), "r"(a[2]), "r"(a[3]), "r"(b[0]), "r"(b[1]));
}

// ---------------- fp32 -> fp16 conversion pass (weights) ----------------
__global__ void tohalf(const float* __restrict__ src, __half* __restrict__ dst,
                       size_t n4) {
    size_t i = (size_t)blockIdx.x * blockDim.x + threadIdx.x;
    if (i < n4) {
        float4 v = ((const float4*)src)[i];
        ((__half2*)dst)[2 * i]     = __floats2half2_rn(v.x, v.y);
        ((__half2*)dst)[2 * i + 1] = __floats2half2_rn(v.z, v.w);
    }
}

// ---------------- router ----------------
__global__ void router_kernel(const float* __restrict__ x,
                              const float* __restrict__ rw, int N) {
    const int t = blockIdx.x;
    const int tid = threadIdx.x;
    const int lane = tid & 31, warp = tid >> 5;

    __shared__ float xs[H];
    const float4* xv = (const float4*)(x + (size_t)t * H);
    float4* xsv = (float4*)xs;
    for (int i = tid; i < H / 4; i += 256) xsv[i] = xv[i];
    __syncthreads();

    const float* wr = rw + (size_t)warp * H;
    float s = 0.f;
    for (int i = lane; i < H; i += 32) s += xs[i] * wr[i];
    #pragma unroll
    for (int o = 16; o; o >>= 1) s += __shfl_xor_sync(0xffffffffu, s, o);

    __shared__ float logits[E];
    if (lane == 0) logits[warp] = s;
    __syncthreads();

    if (tid == 0) {
        float m = logits[0];
        #pragma unroll
        for (int e = 1; e < E; e++) m = fmaxf(m, logits[e]);
        float p[E], den = 0.f;
        #pragma unroll
        for (int e = 0; e < E; e++) { p[e] = __expf(logits[e] - m); den += p[e]; }
        float inv = 1.f / den;
        #pragma unroll
        for (int e = 0; e < E; e++) p[e] *= inv;
        int i0 = 0;
        #pragma unroll
        for (int e = 1; e < E; e++) if (p[e] > p[i0]) i0 = e;
        int i1 = (i0 == 0) ? 1 : 0;
        #pragma unroll
        for (int e = 0; e < E; e++) if (e != i0 && p[e] > p[i1]) i1 = e;
        g_entry_expert[t]     = i0; g_entry_prob[t]     = p[i0];
        g_entry_expert[N + t] = i1; g_entry_prob[N + t] = p[i1];
    }
}

// ---------------- capacity scan: warp-per-expert ballot rank ----------------
__global__ void assign_kernel(int N) {
    const int NK = TOPK * N;                    // 4096
    const int tid = threadIdx.x;
    const int lane = tid & 31, warp = tid >> 5;

    __shared__ int se[2 * 2048];
    for (int i = tid; i < NSLOT; i += blockDim.x) g_slot_token[i] = -1;
    for (int i = tid; i < NK; i += blockDim.x) se[i] = g_entry_expert[i];
    __syncthreads();

    if (warp < E) {
        const int e = warp;
        const unsigned lt = (1u << lane) - 1u;
        int cnt = 0;
        for (int base = 0; base < NK; base += 32) {
            const int idx = base + lane;
            const bool match = (idx < NK) && (se[idx] == e);
            const unsigned m = __ballot_sync(0xffffffffu, match);
            if (match) {
                const int pos = cnt + __popc(m & lt);
                if (pos < CAP) {
                    const int d = e * CAP + pos;
                    g_entry_dest[idx] = d;
                    g_slot_token[d] = idx % N;
                } else {
                    g_entry_dest[idx] = -1;
                }
            }
            cnt += __popc(m);
        }
    }
}

// ---------------- gather tokens (fp16) into dispatch buffer ----------------
__global__ void dispatch_kernel(const float* __restrict__ x) {
    const int slot = blockIdx.x;
    const int t = g_slot_token[slot];
    __half2* dst = (__half2*)(g_bufh + (size_t)slot * H);
    if (t >= 0) {
        const float4* src = (const float4*)(x + (size_t)t * H);
        for (int i = threadIdx.x; i < H / 4; i += blockDim.x) {
            float4 v = src[i];
            dst[2 * i]     = __floats2half2_rn(v.x, v.y);
            dst[2 * i + 1] = __floats2half2_rn(v.z, v.w);
        }
    } else {
        const __half2 z = __floats2half2_rn(0.f, 0.f);
        for (int i = threadIdx.x; i < H / 4; i += blockDim.x) {
            dst[2 * i] = z; dst[2 * i + 1] = z;
        }
    }
}

// ---------------- FP16 mma.sync GEMM, ldmatrix, 16 warps ----------------
// Block 128x256x64, 16 warps (2M x 8N), warp tile 64x32 (4x4 m16n8k16).
// Smem pitch 144 (128B data + 16B pad): conflict-free ldmatrix phases.
// 3-stage cp.async pipeline across K-tiles.
#define BM 128
#define BN 256
#define BK 64
#define PITCH 144
#define STAGES 3
#define STAGE_BYTES ((BM + BN) * PITCH)          // 55296
#define GEMM_SMEM (STAGES * STAGE_BYTES)         // 165888
#define GTHREADS 512

template<bool GELU, typename CT>
__global__ __launch_bounds__(GTHREADS, 1)
void gemm_h(const __half* __restrict__ A, const __half* __restrict__ B,
            const float* __restrict__ bias, CT* __restrict__ C,
            int Ncols, int K) {
    extern __shared__ char smraw[];
    const uint32_t sbase = smem_u32(smraw);
    const int tid = threadIdx.x, lane = tid & 31, wid = tid >> 5;
    const int wm = wid & 1, wn = wid >> 1;       // 2(M) x 8(N), warp tile 64x32
    const int bm = blockIdx.y * BM, bn = blockIdx.x * BN;
    const int lr = lane >> 2, lc = lane & 3;
    const int KT = K / BK;

    float acc[4][4][4];
    #pragma unroll
    for (int i = 0; i < 4; i++)
        #pragma unroll
        for (int j = 0; j < 4; j++)
            #pragma unroll
            for (int q = 0; q < 4; q++) acc[i][j][q] = 0.f;

    // ldmatrix per-lane offsets (within a stage):
    // A x4 (one 16x16 tile): g=lane>>3: row += (g&1)*8, kbyte += (g>>1)*16
    // B x4 (two 8x16 tiles): row += (g>>1)*8, kbyte += (g&1)*16
    const int g = lane >> 3, li = lane & 7;
    const uint32_t aOff = (uint32_t)(wm * 64 + (g & 1) * 8 + li) * PITCH + ((g >> 1) << 4);
    const uint32_t bOff = (uint32_t)(wn * 32 + (g >> 1) * 8 + li) * PITCH + ((g & 1) << 4)
                        + BM * PITCH;

    const int lrow = tid >> 3;        // 0..63
    const int lch  = tid & 7;         // 16B chunk in 128B row
    auto load_stage = [&](int t, int s) {
        const int k0 = t * BK;
        const uint32_t stA = sbase + s * STAGE_BYTES;
        const uint32_t stB = stA + BM * PITCH;
        #pragma unroll
        for (int l = 0; l < 2; l++) {
            const int row = lrow + l * 64;
            cp16(stA + row * PITCH + lch * 16, A + (size_t)(bm + row) * K + k0 + lch * 8);
        }
        #pragma unroll
        for (int l = 0; l < 4; l++) {
            const int row = lrow + l * 64;
            cp16(stB + row * PITCH + lch * 16, B + (size_t)(bn + row) * K + k0 + lch * 8);
        }
    };

    #pragma unroll
    for (int t = 0; t < STAGES - 1; t++) {
        load_stage(t, t);
        asm volatile("cp.async.commit_group;" ::: "memory");
    }

    for (int t = 0; t < KT; t++) {
        asm volatile("cp.async.wait_group %0;" :: "n"(STAGES - 2) : "memory");
        __syncthreads();

        const int tn = t + STAGES - 1;
        if (tn < KT) load_stage(tn, tn % STAGES);
        asm volatile("cp.async.commit_group;" ::: "memory");

        const uint32_t stBase = sbase + (uint32_t)(t % STAGES) * STAGE_BYTES;
        const uint32_t aBase = stBase + aOff;
        const uint32_t bBase = stBase + bOff;

        #pragma unroll
        for (int ks = 0; ks < 4; ks++) {         // four k16 steps per BK=64
            uint32_t a[4][4], b[4][2];
            const uint32_t kb = (uint32_t)ks * 32;
            #pragma unroll
            for (int mt = 0; mt < 4; mt++)
                ldsm_x4(a[mt], aBase + mt * (16 * PITCH) + kb);
            #pragma unroll
            for (int ntp = 0; ntp < 2; ntp++) {
                uint32_t r[4];
                ldsm_x4(r, bBase + ntp * (16 * PITCH) + kb);
                b[2 * ntp][0] = r[0]; b[2 * ntp][1] = r[1];
                b[2 * ntp + 1][0] = r[2]; b[2 * ntp + 1][1] = r[3];
            }
            #pragma unroll
            for (int mt = 0; mt < 4; mt++)
                #pragma unroll
                for (int nt = 0; nt < 4; nt++)
                    mma_f16(acc[mt][nt], a[mt], b[nt]);
        }
    }

    // epilogue: bias (+GELU); CT = __half (GEMM1) or float (GEMM2)
    #pragma unroll
    for (int nt = 0; nt < 4; nt++) {
        const int col = bn + wn * 32 + nt * 8 + 2 * lc;
        const float b0 = __ldg(&bias[col]), b1 = __ldg(&bias[col + 1]);
        #pragma unroll
        for (int mt = 0; mt < 4; mt++) {
            const int row0 = bm + wm * 64 + mt * 16 + lr;
            float v0 = acc[mt][nt][0] + b0;
            float v1 = acc[mt][nt][1] + b1;
            float v2 = acc[mt][nt][2] + b0;
            float v3 = acc[mt][nt][3] + b1;
            if (GELU) {
                v0 = 0.5f * v0 * (1.f + erff(v0 * 0.7071067811865475f));
                v1 = 0.5f * v1 * (1.f + erff(v1 * 0.7071067811865475f));
                v2 = 0.5f * v2 * (1.f + erff(v2 * 0.7071067811865475f));
                v3 = 0.5f * v3 * (1.f + erff(v3 * 0.7071067811865475f));
            }
            if (sizeof(CT) == 2) {
                __half2* c0 = (__half2*)((__half*)C + (size_t)row0 * Ncols + col);
                __half2* c1 = (__half2*)((__half*)C + (size_t)(row0 + 8) * Ncols + col);
                *c0 = __floats2half2_rn(v0, v1);
                *c1 = __floats2half2_rn(v2, v3);
            } else {
                *(float2*)((float*)C + (size_t)row0 * Ncols + col)       = make_float2(v0, v1);
                *(float2*)((float*)C + (size_t)(row0 + 8) * Ncols + col) = make_float2(v2, v3);
            }
        }
    }
}

// ---------------- weighted combine ----------------
__global__ void combine_kernel(int N, float* __restrict__ out) {
    const int t = blockIdx.x;
    const int d0 = g_entry_dest[t];
    const int d1 = g_entry_dest[N + t];
    const float p0 = g_entry_prob[t];
    const float p1 = g_entry_prob[N + t];
    const float4* h0 = (d0 >= 0) ? (const float4*)(g_h + (size_t)d0 * H) : nullptr;
    const float4* h1 = (d1 >= 0) ? (const float4*)(g_h + (size_t)d1 * H) : nullptr;
    float4* o = (float4*)(out + (size_t)t * H);
    for (int i = threadIdx.x; i < H / 4; i += blockDim.x) {
        float4 acc = make_float4(0.f, 0.f, 0.f, 0.f);
        if (h0) { float4 v = h0[i]; acc.x += p0*v.x; acc.y += p0*v.y; acc.z += p0*v.z; acc.w += p0*v.w; }
        if (h1) { float4 v = h1[i]; acc.x += p1*v.x; acc.y += p1*v.y; acc.z += p1*v.z; acc.w += p1*v.w; }
        o[i] = acc;
    }
}

// ---------------- launch ----------------
extern "C" void kernel_launch(void* const* d_in, const int* in_sizes, int n_in,
                              void* d_out, int out_size) {
    const float* x  = (const float*)d_in[0];
    const float* rw = (const float*)d_in[1];
    const float* w1 = (const float*)d_in[2];
    const float* b1 = (const float*)d_in[3];
    const float* w2 = (const float*)d_in[4];
    const float* b2 = (const float*)d_in[5];
    float* out = (float*)d_out;

    const int N = in_sizes[0] / H;   // 2048

    __half* bufh; cudaGetSymbolAddress((void**)&bufh, g_bufh);
    __half* acth; cudaGetSymbolAddress((void**)&acth, g_acth);
    __half* w1h;  cudaGetSymbolAddress((void**)&w1h, g_w1h);
    __half* w2h;  cudaGetSymbolAddress((void**)&w2h, g_w2h);
    float*  hbf;  cudaGetSymbolAddress((void**)&hbf, g_h);

    cudaFuncSetAttribute(gemm_h<true, __half>,
                         cudaFuncAttributeMaxDynamicSharedMemorySize, GEMM_SMEM);
    cudaFuncSetAttribute(gemm_h<false, float>,
                         cudaFuncAttributeMaxDynamicSharedMemorySize, GEMM_SMEM);

    {   // weight fp16 conversion
        size_t n4 = (size_t)F * H / 4;
        tohalf<<<(unsigned)((n4 + 255) / 256), 256>>>(w1, w1h, n4);
        tohalf<<<(unsigned)((n4 + 255) / 256), 256>>>(w2, w2h, n4);
    }

    router_kernel<<<N, 256>>>(x, rw, N);
    assign_kernel<<<1, 256>>>(N);
    dispatch_kernel<<<NSLOT, 256>>>(x);

    // GEMM1: buf[4096,2048] @ w1h^T -> gelu -> act (fp16)
    gemm_h<true, __half><<<dim3(F / BN, NSLOT / BM), GTHREADS, GEMM_SMEM>>>(
        bufh, w1h, b1, acth, F, H);
    // GEMM2: act[4096,8192] @ w2h^T + b2 -> h (fp32)
    gemm_h<false, float><<<dim3(H / BN, NSLOT / BM), GTHREADS, GEMM_SMEM>>>(
        acth, w2h, b2, hbf, H, F);

    combine_kernel<<<N, 256>>>(N, out);
}

// round 12
// speedup vs baseline: 7.9220x; 1.0146x over previous
#include <cuda_runtime.h>
#include <cuda_fp16.h>
#include <cstdint>
#include <math.h>

#define E 8
#define TOPK 2
#define CAP 512
#define H 2048
#define F 8192
#define NSLOT (E*CAP)   // 4096

// ---------------- scratch (no allocation allowed) ----------------
__device__ __half g_xh[(size_t)2048 * H];     // fp16 copy of tokens
__device__ __half g_acth[(size_t)NSLOT * F];  // gelu acts fp16
__device__ __half g_w1h[(size_t)F * H];       // w1 fp16
__device__ __half g_w2h[(size_t)H * F];       // w2 fp16
__device__ float  g_h[(size_t)NSLOT * H];     // expert output fp32
__device__ __half g_zerorow[H];               // zero A-row for dropped slots
__device__ int    g_entry_expert[2 * 2048];
__device__ float  g_entry_prob  [2 * 2048];
__device__ int    g_entry_dest  [2 * 2048];
__device__ int    g_slot_token  [NSLOT];

// ---------------- helpers ----------------
__device__ __forceinline__ uint32_t smem_u32(const void* p) {
    uint32_t a;
    asm("{ .reg .u64 t; cvta.to.shared.u64 t, %1; cvt.u32.u64 %0, t; }"
        : "=r"(a) : "l"(p));
    return a;
}
__device__ __forceinline__ void cp16(uint32_t dst, const void* src) {
    asm volatile("cp.async.cg.shared.global [%0], [%1], 16;"
                 :: "r"(dst), "l"(src) : "memory");
}
__device__ __forceinline__ void ldsm_x4(uint32_t* r, uint32_t addr) {
    asm volatile("ldmatrix.sync.aligned.m8n8.x4.shared.b16 {%0,%1,%2,%3}, [%4];"
                 : "=r"(r[0]), "=r"(r[1]), "=r"(r[2]), "=r"(r[3]) : "r"(addr));
}
__device__ __forceinline__ void mma_f16(float* c, const uint32_t* a, const uint32_t* b) {
    asm volatile(
        "mma.sync.aligned.m16n8k16.row.col.f32.f16.f16.f32 "
        "{%0,%1,%2,%3}, {%4,%5,%6,%7}, {%8,%9}, {%0,%1,%2,%3};"
        : "+f"(c[0]), "+f"(c[1]), "+f"(c[2]), "+f"(c[3])
        : "r"(a[0]), "r"(a[1]), "r"(a[2]), "r"(a[3]), "r"(b[0]), "r"(b[1]));
}

// ---------------- fp32 -> fp16 conversion pass ----------------
__global__ void tohalf(const float* __restrict__ src, __half* __restrict__ dst,
                       size_t n4) {
    size_t i = (size_t)blockIdx.x * blockDim.x + threadIdx.x;
    if (i < n4) {
        float4 v = ((const float4*)src)[i];
        ((__half2*)dst)[2 * i]     = __floats2half2_rn(v.x, v.y);
        ((__half2*)dst)[2 * i + 1] = __floats2half2_rn(v.z, v.w);
    }
}

// ---------------- router ----------------
__global__ void router_kernel(const float* __restrict__ x,
                              const float* __restrict__ rw, int N) {
    const int t = blockIdx.x;
    const int tid = threadIdx.x;
    const int lane = tid & 31, warp = tid >> 5;

    __shared__ float xs[H];
    const float4* xv = (const float4*)(x + (size_t)t * H);
    float4* xsv = (float4*)xs;
    for (int i = tid; i < H / 4; i += 256) xsv[i] = xv[i];
    __syncthreads();

    const float* wr = rw + (size_t)warp * H;
    float s = 0.f;
    for (int i = lane; i < H; i += 32) s += xs[i] * wr[i];
    #pragma unroll
    for (int o = 16; o; o >>= 1) s += __shfl_xor_sync(0xffffffffu, s, o);

    __shared__ float logits[E];
    if (lane == 0) logits[warp] = s;
    __syncthreads();

    if (tid == 0) {
        float m = logits[0];
        #pragma unroll
        for (int e = 1; e < E; e++) m = fmaxf(m, logits[e]);
        float p[E], den = 0.f;
        #pragma unroll
        for (int e = 0; e < E; e++) { p[e] = __expf(logits[e] - m); den += p[e]; }
        float inv = 1.f / den;
        #pragma unroll
        for (int e = 0; e < E; e++) p[e] *= inv;
        int i0 = 0;
        #pragma unroll
        for (int e = 1; e < E; e++) if (p[e] > p[i0]) i0 = e;
        int i1 = (i0 == 0) ? 1 : 0;
        #pragma unroll
        for (int e = 0; e < E; e++) if (e != i0 && p[e] > p[i1]) i1 = e;
        g_entry_expert[t]     = i0; g_entry_prob[t]     = p[i0];
        g_entry_expert[N + t] = i1; g_entry_prob[N + t] = p[i1];
    }
}

// ---------------- capacity scan: warp-per-expert ballot rank (4x unrolled) ----------------
__global__ void assign_kernel(int N) {
    const int NK = TOPK * N;                    // 4096
    const int tid = threadIdx.x;
    const int lane = tid & 31, warp = tid >> 5;

    __shared__ int se[2 * 2048];
    for (int i = tid; i < NSLOT; i += blockDim.x) g_slot_token[i] = -1;
    for (int i = tid; i < NK; i += blockDim.x) se[i] = g_entry_expert[i];
    __syncthreads();

    if (warp < E) {
        const int e = warp;
        const unsigned lt = (1u << lane) - 1u;
        int cnt = 0;
        for (int base = 0; base < NK; base += 128) {
            unsigned m[4];
            int v[4];
            #pragma unroll
            for (int j = 0; j < 4; j++) v[j] = se[base + j * 32 + lane];
            #pragma unroll
            for (int j = 0; j < 4; j++) m[j] = __ballot_sync(0xffffffffu, v[j] == e);
            #pragma unroll
            for (int j = 0; j < 4; j++) {
                if (v[j] == e) {
                    const int idx = base + j * 32 + lane;
                    const int pos = cnt + __popc(m[j] & lt);
                    if (pos < CAP) {
                        const int d = e * CAP + pos;
                        g_entry_dest[idx] = d;
                        g_slot_token[d] = idx % N;
                    } else {
                        g_entry_dest[idx] = -1;
                    }
                }
                cnt += __popc(m[j]);
            }
        }
    }
}

// ---------------- FP16 mma.sync GEMM, ldmatrix, 16 warps ----------------
// Block 128x256x64, 16 warps (2M x 8N), warp tile 64x32 (4x4 m16n8k16).
// Smem pitch 144: conflict-free ldmatrix phases. 4-stage cp.async pipeline.
// GATHER=true: A rows come from xh[token] via per-CTA slot->token table
// (dropped slots read g_zerorow).
#define BM 128
#define BN 256
#define BK 64
#define PITCH 144
#define STAGES 4
#define STAGE_BYTES ((BM + BN) * PITCH)          // 55296
#define GEMM_SMEM (STAGES * STAGE_BYTES)         // 221184
#define GTHREADS 512

template<bool GELU, bool GATHER, typename CT>
__global__ __launch_bounds__(GTHREADS, 1)
void gemm_h(const __half* __restrict__ A, const __half* __restrict__ B,
            const float* __restrict__ bias, CT* __restrict__ C,
            int Ncols, int K, const int* __restrict__ slot_token,
            const __half* __restrict__ zerorow) {
    extern __shared__ char smraw[];
    __shared__ int tok[BM];
    const uint32_t sbase = smem_u32(smraw);
    const int tid = threadIdx.x, lane = tid & 31, wid = tid >> 5;
    const int wm = wid & 1, wn = wid >> 1;       // 2(M) x 8(N), warp tile 64x32
    const int bm = blockIdx.y * BM, bn = blockIdx.x * BN;
    const int lr = lane >> 2, lc = lane & 3;
    const int KT = K / BK;

    if (GATHER) {
        if (tid < BM) tok[tid] = slot_token[bm + tid];
        __syncthreads();
    }

    const int lrow = tid >> 3;        // 0..63
    const int lch  = tid & 7;         // 16B chunk in 128B row

    // per-thread A row sources (rows lrow and lrow+64), fixed for the kernel
    const __half* aRow[2];
    #pragma unroll
    for (int l = 0; l < 2; l++) {
        const int row = lrow + l * 64;
        if (GATHER) {
            const int t = tok[row];
            aRow[l] = (t >= 0) ? A + (size_t)t * K : zerorow;
        } else {
            aRow[l] = A + (size_t)(bm + row) * K;
        }
    }

    float acc[4][4][4];
    #pragma unroll
    for (int i = 0; i < 4; i++)
        #pragma unroll
        for (int j = 0; j < 4; j++)
            #pragma unroll
            for (int q = 0; q < 4; q++) acc[i][j][q] = 0.f;

    const int g = lane >> 3, li = lane & 7;
    const uint32_t aOff = (uint32_t)(wm * 64 + (g & 1) * 8 + li) * PITCH + ((g >> 1) << 4);
    const uint32_t bOff = (uint32_t)(wn * 32 + (g >> 1) * 8 + li) * PITCH + ((g & 1) << 4)
                        + BM * PITCH;

    auto load_stage = [&](int t, int s) {
        const int k0 = t * BK;
        const uint32_t stA = sbase + s * STAGE_BYTES;
        const uint32_t stB = stA + BM * PITCH;
        #pragma unroll
        for (int l = 0; l < 2; l++) {
            const int row = lrow + l * 64;
            cp16(stA + row * PITCH + lch * 16, aRow[l] + k0 + lch * 8);
        }
        #pragma unroll
        for (int l = 0; l < 4; l++) {
            const int row = lrow + l * 64;
            cp16(stB + row * PITCH + lch * 16, B + (size_t)(bn + row) * K + k0 + lch * 8);
        }
    };

    #pragma unroll
    for (int t = 0; t < STAGES - 1; t++) {
        load_stage(t, t);
        asm volatile("cp.async.commit_group;" ::: "memory");
    }

    for (int t = 0; t < KT; t++) {
        asm volatile("cp.async.wait_group %0;" :: "n"(STAGES - 2) : "memory");
        __syncthreads();

        const int tn = t + STAGES - 1;
        if (tn < KT) load_stage(tn, tn % STAGES);
        asm volatile("cp.async.commit_group;" ::: "memory");

        const uint32_t stBase = sbase + (uint32_t)(t % STAGES) * STAGE_BYTES;
        const uint32_t aBase = stBase + aOff;
        const uint32_t bBase = stBase + bOff;

        #pragma unroll
        for (int ks = 0; ks < 4; ks++) {         // four k16 steps per BK=64
            uint32_t a[4][4], b[4][2];
            const uint32_t kb = (uint32_t)ks * 32;
            #pragma unroll
            for (int mt = 0; mt < 4; mt++)
                ldsm_x4(a[mt], aBase + mt * (16 * PITCH) + kb);
            #pragma unroll
            for (int ntp = 0; ntp < 2; ntp++) {
                uint32_t r[4];
                ldsm_x4(r, bBase + ntp * (16 * PITCH) + kb);
                b[2 * ntp][0] = r[0]; b[2 * ntp][1] = r[1];
                b[2 * ntp + 1][0] = r[2]; b[2 * ntp + 1][1] = r[3];
            }
            #pragma unroll
            for (int mt = 0; mt < 4; mt++)
                #pragma unroll
                for (int nt = 0; nt < 4; nt++)
                    mma_f16(acc[mt][nt], a[mt], b[nt]);
        }
    }

    // epilogue: bias (+GELU); CT = __half (GEMM1) or float (GEMM2)
    #pragma unroll
    for (int nt = 0; nt < 4; nt++) {
        const int col = bn + wn * 32 + nt * 8 + 2 * lc;
        const float b0 = __ldg(&bias[col]), b1 = __ldg(&bias[col + 1]);
        #pragma unroll
        for (int mt = 0; mt < 4; mt++) {
            const int row0 = bm + wm * 64 + mt * 16 + lr;
            float v0 = acc[mt][nt][0] + b0;
            float v1 = acc[mt][nt][1] + b1;
            float v2 = acc[mt][nt][2] + b0;
            float v3 = acc[mt][nt][3] + b1;
            if (GELU) {
                v0 = 0.5f * v0 * (1.f + erff(v0 * 0.7071067811865475f));
                v1 = 0.5f * v1 * (1.f + erff(v1 * 0.7071067811865475f));
                v2 = 0.5f * v2 * (1.f + erff(v2 * 0.7071067811865475f));
                v3 = 0.5f * v3 * (1.f + erff(v3 * 0.7071067811865475f));
            }
            if (sizeof(CT) == 2) {
                __half2* c0 = (__half2*)((__half*)C + (size_t)row0 * Ncols + col);
                __half2* c1 = (__half2*)((__half*)C + (size_t)(row0 + 8) * Ncols + col);
                *c0 = __floats2half2_rn(v0, v1);
                *c1 = __floats2half2_rn(v2, v3);
            } else {
                *(float2*)((float*)C + (size_t)row0 * Ncols + col)       = make_float2(v0, v1);
                *(float2*)((float*)C + (size_t)(row0 + 8) * Ncols + col) = make_float2(v2, v3);
            }
        }
    }
}

// ---------------- weighted combine ----------------
__global__ void combine_kernel(int N, float* __restrict__ out) {
    const int t = blockIdx.x;
    const int d0 = g_entry_dest[t];
    const int d1 = g_entry_dest[N + t];
    const float p0 = g_entry_prob[t];
    const float p1 = g_entry_prob[N + t];
    const float4* h0 = (d0 >= 0) ? (const float4*)(g_h + (size_t)d0 * H) : nullptr;
    const float4* h1 = (d1 >= 0) ? (const float4*)(g_h + (size_t)d1 * H) : nullptr;
    float4* o = (float4*)(out + (size_t)t * H);
    for (int i = threadIdx.x; i < H / 4; i += blockDim.x) {
        float4 acc = make_float4(0.f, 0.f, 0.f, 0.f);
        if (h0) { float4 v = h0[i]; acc.x += p0*v.x; acc.y += p0*v.y; acc.z += p0*v.z; acc.w += p0*v.w; }
        if (h1) { float4 v = h1[i]; acc.x += p1*v.x; acc.y += p1*v.y; acc.z += p1*v.z; acc.w += p1*v.w; }
        o[i] = acc;
    }
}

// ---------------- launch ----------------
extern "C" void kernel_launch(void* const* d_in, const int* in_sizes, int n_in,
                              void* d_out, int out_size) {
    const float* x  = (const float*)d_in[0];
    const float* rw = (const float*)d_in[1];
    const float* w1 = (const float*)d_in[2];
    const float* b1 = (const float*)d_in[3];
    const float* w2 = (const float*)d_in[4];
    const float* b2 = (const float*)d_in[5];
    float* out = (float*)d_out;

    const int N = in_sizes[0] / H;   // 2048

    __half* xh;   cudaGetSymbolAddress((void**)&xh, g_xh);
    __half* acth; cudaGetSymbolAddress((void**)&acth, g_acth);
    __half* w1h;  cudaGetSymbolAddress((void**)&w1h, g_w1h);
    __half* w2h;  cudaGetSymbolAddress((void**)&w2h, g_w2h);
    float*  hbf;  cudaGetSymbolAddress((void**)&hbf, g_h);
    __half* zrow; cudaGetSymbolAddress((void**)&zrow, g_zerorow);
    int* stok;    cudaGetSymbolAddress((void**)&stok, g_slot_token);

    cudaFuncSetAttribute(gemm_h<true, true, __half>,
                         cudaFuncAttributeMaxDynamicSharedMemorySize, GEMM_SMEM);
    cudaFuncSetAttribute(gemm_h<false, false, float>,
                         cudaFuncAttributeMaxDynamicSharedMemorySize, GEMM_SMEM);

    {   // fp16 conversions (weights + tokens)
        size_t n4 = (size_t)F * H / 4;
        tohalf<<<(unsigned)((n4 + 255) / 256), 256>>>(w1, w1h, n4);
        tohalf<<<(unsigned)((n4 + 255) / 256), 256>>>(w2, w2h, n4);
        size_t x4 = (size_t)N * H / 4;
        tohalf<<<(unsigned)((x4 + 255) / 256), 256>>>(x, xh, x4);
    }

    router_kernel<<<N, 256>>>(x, rw, N);
    assign_kernel<<<1, 256>>>(N);

    // GEMM1 (gather A from xh via slot->token): -> gelu -> act (fp16)
    gemm_h<true, true, __half><<<dim3(F / BN, NSLOT / BM), GTHREADS, GEMM_SMEM>>>(
        xh, w1h, b1, acth, F, H, stok, zrow);
    // GEMM2: act[4096,8192] @ w2h^T + b2 -> h (fp32)
    gemm_h<false, false, float><<<dim3(H / BN, NSLOT / BM), GTHREADS, GEMM_SMEM>>>(
        acth, w2h, b2, hbf, H, F, nullptr, nullptr);

    combine_kernel<<<N, 256>>>(N, out);
}

// round 13
// speedup vs baseline: 8.1069x; 1.0233x over previous
#include <cuda_runtime.h>
#include <cuda_fp16.h>
#include <cstdint>
#include <math.h>

#define E 8
#define TOPK 2
#define CAP 512
#define H 2048
#define F 8192
#define NSLOT (E*CAP)   // 4096

// ---------------- scratch (no allocation allowed) ----------------
__device__ __half g_xh[(size_t)2048 * H];     // fp16 copy of tokens
__device__ __half g_acth[(size_t)NSLOT * F];  // gelu acts fp16
__device__ __half g_w1h[(size_t)F * H];       // w1 fp16
__device__ __half g_w2h[(size_t)H * F];       // w2 fp16
__device__ float  g_h[(size_t)NSLOT * H];     // expert output fp32
__device__ __half g_zerorow[H];               // zero A-row for dropped slots
__device__ int    g_entry_expert[2 * 2048];
__device__ float  g_entry_prob  [2 * 2048];
__device__ int    g_entry_dest  [2 * 2048];
__device__ int    g_slot_token  [NSLOT];

// ---------------- helpers ----------------
__device__ __forceinline__ uint32_t smem_u32(const void* p) {
    uint32_t a;
    asm("{ .reg .u64 t; cvta.to.shared.u64 t, %1; cvt.u32.u64 %0, t; }"
        : "=r"(a) : "l"(p));
    return a;
}
__device__ __forceinline__ void cp16(uint32_t dst, const void* src) {
    asm volatile("cp.async.cg.shared.global [%0], [%1], 16;"
                 :: "r"(dst), "l"(src) : "memory");
}
__device__ __forceinline__ void ldsm_x4(uint32_t* r, uint32_t addr) {
    asm volatile("ldmatrix.sync.aligned.m8n8.x4.shared.b16 {%0,%1,%2,%3}, [%4];"
                 : "=r"(r[0]), "=r"(r[1]), "=r"(r[2]), "=r"(r[3]) : "r"(addr));
}
__device__ __forceinline__ void mma_f16(float* c, const uint32_t* a, const uint32_t* b) {
    asm volatile(
        "mma.sync.aligned.m16n8k16.row.col.f32.f16.f16.f32 "
        "{%0,%1,%2,%3}, {%4,%5,%6,%7}, {%8,%9}, {%0,%1,%2,%3};"
        : "+f"(c[0]), "+f"(c[1]), "+f"(c[2]), "+f"(c[3])
        : "r"(a[0]), "r"(a[1]), "r"(a[2]), "r"(a[3]), "r"(b[0]), "r"(b[1]));
}

// ---------------- fp32 -> fp16 conversion pass (weights) ----------------
__global__ void tohalf(const float* __restrict__ src, __half* __restrict__ dst,
                       size_t n4) {
    size_t i = (size_t)blockIdx.x * blockDim.x + threadIdx.x;
    if (i < n4) {
        float4 v = ((const float4*)src)[i];
        ((__half2*)dst)[2 * i]     = __floats2half2_rn(v.x, v.y);
        ((__half2*)dst)[2 * i + 1] = __floats2half2_rn(v.z, v.w);
    }
}

// ---------------- router (also emits fp16 token copy) ----------------
__global__ void router_kernel(const float* __restrict__ x,
                              const float* __restrict__ rw,
                              __half* __restrict__ xh, int N) {
    const int t = blockIdx.x;
    const int tid = threadIdx.x;
    const int lane = tid & 31, warp = tid >> 5;

    __shared__ float xs[H];
    const float4* xv = (const float4*)(x + (size_t)t * H);
    float4* xsv = (float4*)xs;
    for (int i = tid; i < H / 4; i += 256) xsv[i] = xv[i];
    __syncthreads();

    // fp16 writeback from smem
    {
        __half2* dst = (__half2*)(xh + (size_t)t * H);
        for (int i = tid; i < H / 4; i += 256) {
            float4 v = xsv[i];
            dst[2 * i]     = __floats2half2_rn(v.x, v.y);
            dst[2 * i + 1] = __floats2half2_rn(v.z, v.w);
        }
    }

    const float* wr = rw + (size_t)warp * H;
    float s = 0.f;
    for (int i = lane; i < H; i += 32) s += xs[i] * wr[i];
    #pragma unroll
    for (int o = 16; o; o >>= 1) s += __shfl_xor_sync(0xffffffffu, s, o);

    __shared__ float logits[E];
    if (lane == 0) logits[warp] = s;
    __syncthreads();

    if (tid == 0) {
        float m = logits[0];
        #pragma unroll
        for (int e = 1; e < E; e++) m = fmaxf(m, logits[e]);
        float p[E], den = 0.f;
        #pragma unroll
        for (int e = 0; e < E; e++) { p[e] = __expf(logits[e] - m); den += p[e]; }
        float inv = 1.f / den;
        #pragma unroll
        for (int e = 0; e < E; e++) p[e] *= inv;
        int i0 = 0;
        #pragma unroll
        for (int e = 1; e < E; e++) if (p[e] > p[i0]) i0 = e;
        int i1 = (i0 == 0) ? 1 : 0;
        #pragma unroll
        for (int e = 0; e < E; e++) if (e != i0 && p[e] > p[i1]) i1 = e;
        g_entry_expert[t]     = i0; g_entry_prob[t]     = p[i0];
        g_entry_expert[N + t] = i1; g_entry_prob[N + t] = p[i1];
    }
}

// ---------------- capacity scan: warp-per-expert ballot rank (4x unrolled) ----------------
__global__ void assign_kernel(int N) {
    const int NK = TOPK * N;                    // 4096
    const int tid = threadIdx.x;
    const int lane = tid & 31, warp = tid >> 5;

    __shared__ int se[2 * 2048];
    for (int i = tid; i < NSLOT; i += blockDim.x) g_slot_token[i] = -1;
    for (int i = tid; i < NK; i += blockDim.x) se[i] = g_entry_expert[i];
    __syncthreads();

    if (warp < E) {
        const int e = warp;
        const unsigned lt = (1u << lane) - 1u;
        int cnt = 0;
        for (int base = 0; base < NK; base += 128) {
            unsigned m[4];
            int v[4];
            #pragma unroll
            for (int j = 0; j < 4; j++) v[j] = se[base + j * 32 + lane];
            #pragma unroll
            for (int j = 0; j < 4; j++) m[j] = __ballot_sync(0xffffffffu, v[j] == e);
            #pragma unroll
            for (int j = 0; j < 4; j++) {
                if (v[j] == e) {
                    const int idx = base + j * 32 + lane;
                    const int pos = cnt + __popc(m[j] & lt);
                    if (pos < CAP) {
                        const int d = e * CAP + pos;
                        g_entry_dest[idx] = d;
                        g_slot_token[d] = idx % N;
                    } else {
                        g_entry_dest[idx] = -1;
                    }
                }
                cnt += __popc(m[j]);
            }
        }
    }
}

// ---------------- FP16 mma.sync GEMM, ldmatrix, 2 CTAs/SM ----------------
// Block 128x128x64, 8 warps (2M x 4N), warp tile 64x32 (4x4 m16n8k16).
// Smem pitch 144: conflict-free ldmatrix phases. 3-stage cp.async pipeline.
// 108KB smem/CTA -> 2 CTAs/SM = two independent barrier domains per SM.
#define BM 128
#define BN 128
#define BK 64
#define PITCH 144
#define STAGES 3
#define STAGE_BYTES ((BM + BN) * PITCH)          // 36864
#define GEMM_SMEM (STAGES * STAGE_BYTES)         // 110592
#define GTHREADS 256

template<bool GELU, bool GATHER, typename CT>
__global__ __launch_bounds__(GTHREADS, 2)
void gemm_h(const __half* __restrict__ A, const __half* __restrict__ B,
            const float* __restrict__ bias, CT* __restrict__ C,
            int Ncols, int K, const int* __restrict__ slot_token,
            const __half* __restrict__ zerorow) {
    extern __shared__ char smraw[];
    __shared__ int tok[BM];
    const uint32_t sbase = smem_u32(smraw);
    const int tid = threadIdx.x, lane = tid & 31, wid = tid >> 5;
    const int wm = wid & 1, wn = wid >> 1;       // 2(M) x 4(N), warp tile 64x32
    const int bm = blockIdx.y * BM, bn = blockIdx.x * BN;
    const int lr = lane >> 2, lc = lane & 3;
    const int KT = K / BK;

    if (GATHER) {
        if (tid < BM) tok[tid] = slot_token[bm + tid];
        __syncthreads();
    }

    const int lrow = tid >> 3;        // 0..31
    const int lch  = tid & 7;         // 16B chunk in 128B row

    // per-thread A row sources (rows lrow + l*32), fixed for the kernel
    const __half* aRow[4];
    #pragma unroll
    for (int l = 0; l < 4; l++) {
        const int row = lrow + l * 32;
        if (GATHER) {
            const int t = tok[row];
            aRow[l] = (t >= 0) ? A + (size_t)t * K : zerorow;
        } else {
            aRow[l] = A + (size_t)(bm + row) * K;
        }
    }

    float acc[4][4][4];
    #pragma unroll
    for (int i = 0; i < 4; i++)
        #pragma unroll
        for (int j = 0; j < 4; j++)
            #pragma unroll
            for (int q = 0; q < 4; q++) acc[i][j][q] = 0.f;

    const int g = lane >> 3, li = lane & 7;
    const uint32_t aOff = (uint32_t)(wm * 64 + (g & 1) * 8 + li) * PITCH + ((g >> 1) << 4);
    const uint32_t bOff = (uint32_t)(wn * 32 + (g >> 1) * 8 + li) * PITCH + ((g & 1) << 4)
                        + BM * PITCH;

    auto load_stage = [&](int t, int s) {
        const int k0 = t * BK;
        const uint32_t stA = sbase + s * STAGE_BYTES;
        const uint32_t stB = stA + BM * PITCH;
        #pragma unroll
        for (int l = 0; l < 4; l++) {
            const int row = lrow + l * 32;
            cp16(stA + row * PITCH + lch * 16, aRow[l] + k0 + lch * 8);
        }
        #pragma unroll
        for (int l = 0; l < 4; l++) {
            const int row = lrow + l * 32;
            cp16(stB + row * PITCH + lch * 16, B + (size_t)(bn + row) * K + k0 + lch * 8);
        }
    };

    #pragma unroll
    for (int t = 0; t < STAGES - 1; t++) {
        load_stage(t, t);
        asm volatile("cp.async.commit_group;" ::: "memory");
    }

    for (int t = 0; t < KT; t++) {
        asm volatile("cp.async.wait_group %0;" :: "n"(STAGES - 2) : "memory");
        __syncthreads();

        const int tn = t + STAGES - 1;
        if (tn < KT) load_stage(tn, tn % STAGES);
        asm volatile("cp.async.commit_group;" ::: "memory");

        const uint32_t stBase = sbase + (uint32_t)(t % STAGES) * STAGE_BYTES;
        const uint32_t aBase = stBase + aOff;
        const uint32_t bBase = stBase + bOff;

        #pragma unroll
        for (int ks = 0; ks < 4; ks++) {         // four k16 steps per BK=64
            uint32_t a[4][4], b[4][2];
            const uint32_t kb = (uint32_t)ks * 32;
            #pragma unroll
            for (int mt = 0; mt < 4; mt++)
                ldsm_x4(a[mt], aBase + mt * (16 * PITCH) + kb);
            #pragma unroll
            for (int ntp = 0; ntp < 2; ntp++) {
                uint32_t r[4];
                ldsm_x4(r, bBase + ntp * (16 * PITCH) + kb);
                b[2 * ntp][0] = r[0]; b[2 * ntp][1] = r[1];
                b[2 * ntp + 1][0] = r[2]; b[2 * ntp + 1][1] = r[3];
            }
            #pragma unroll
            for (int mt = 0; mt < 4; mt++)
                #pragma unroll
                for (int nt = 0; nt < 4; nt++)
                    mma_f16(acc[mt][nt], a[mt], b[nt]);
        }
    }

    // epilogue: bias (+GELU); CT = __half (GEMM1) or float (GEMM2)
    #pragma unroll
    for (int nt = 0; nt < 4; nt++) {
        const int col = bn + wn * 32 + nt * 8 + 2 * lc;
        const float b0 = __ldg(&bias[col]), b1 = __ldg(&bias[col + 1]);
        #pragma unroll
        for (int mt = 0; mt < 4; mt++) {
            const int row0 = bm + wm * 64 + mt * 16 + lr;
            float v0 = acc[mt][nt][0] + b0;
            float v1 = acc[mt][nt][1] + b1;
            float v2 = acc[mt][nt][2] + b0;
            float v3 = acc[mt][nt][3] + b1;
            if (GELU) {
                v0 = 0.5f * v0 * (1.f + erff(v0 * 0.7071067811865475f));
                v1 = 0.5f * v1 * (1.f + erff(v1 * 0.7071067811865475f));
                v2 = 0.5f * v2 * (1.f + erff(v2 * 0.7071067811865475f));
                v3 = 0.5f * v3 * (1.f + erff(v3 * 0.7071067811865475f));
            }
            if (sizeof(CT) == 2) {
                __half2* c0 = (__half2*)((__half*)C + (size_t)row0 * Ncols + col);
                __half2* c1 = (__half2*)((__half*)C + (size_t)(row0 + 8) * Ncols + col);
                *c0 = __floats2half2_rn(v0, v1);
                *c1 = __floats2half2_rn(v2, v3);
            } else {
                *(float2*)((float*)C + (size_t)row0 * Ncols + col)       = make_float2(v0, v1);
                *(float2*)((float*)C + (size_t)(row0 + 8) * Ncols + col) = make_float2(v2, v3);
            }
        }
    }
}

// ---------------- weighted combine ----------------
__global__ void combine_kernel(int N, float* __restrict__ out) {
    const int t = blockIdx.x;
    const int d0 = g_entry_dest[t];
    const int d1 = g_entry_dest[N + t];
    const float p0 = g_entry_prob[t];
    const float p1 = g_entry_prob[N + t];
    const float4* h0 = (d0 >= 0) ? (const float4*)(g_h + (size_t)d0 * H) : nullptr;
    const float4* h1 = (d1 >= 0) ? (const float4*)(g_h + (size_t)d1 * H) : nullptr;
    float4* o = (float4*)(out + (size_t)t * H);
    for (int i = threadIdx.x; i < H / 4; i += blockDim.x) {
        float4 acc = make_float4(0.f, 0.f, 0.f, 0.f);
        if (h0) { float4 v = h0[i]; acc.x += p0*v.x; acc.y += p0*v.y; acc.z += p0*v.z; acc.w += p0*v.w; }
        if (h1) { float4 v = h1[i]; acc.x += p1*v.x; acc.y += p1*v.y; acc.z += p1*v.z; acc.w += p1*v.w; }
        o[i] = acc;
    }
}

// ---------------- launch ----------------
extern "C" void kernel_launch(void* const* d_in, const int* in_sizes, int n_in,
                              void* d_out, int out_size) {
    const float* x  = (const float*)d_in[0];
    const float* rw = (const float*)d_in[1];
    const float* w1 = (const float*)d_in[2];
    const float* b1 = (const float*)d_in[3];
    const float* w2 = (const float*)d_in[4];
    const float* b2 = (const float*)d_in[5];
    float* out = (float*)d_out;

    const int N = in_sizes[0] / H;   // 2048

    __half* xh;   cudaGetSymbolAddress((void**)&xh, g_xh);
    __half* acth; cudaGetSymbolAddress((void**)&acth, g_acth);
    __half* w1h;  cudaGetSymbolAddress((void**)&w1h, g_w1h);
    __half* w2h;  cudaGetSymbolAddress((void**)&w2h, g_w2h);
    float*  hbf;  cudaGetSymbolAddress((void**)&hbf, g_h);
    __half* zrow; cudaGetSymbolAddress((void**)&zrow, g_zerorow);
    int* stok;    cudaGetSymbolAddress((void**)&stok, g_slot_token);

    cudaFuncSetAttribute(gemm_h<true, true, __half>,
                         cudaFuncAttributeMaxDynamicSharedMemorySize, GEMM_SMEM);
    cudaFuncSetAttribute(gemm_h<false, false, float>,
                         cudaFuncAttributeMaxDynamicSharedMemorySize, GEMM_SMEM);

    {   // weight fp16 conversions
        size_t n4 = (size_t)F * H / 4;
        tohalf<<<(unsigned)((n4 + 255) / 256), 256>>>(w1, w1h, n4);
        tohalf<<<(unsigned)((n4 + 255) / 256), 256>>>(w2, w2h, n4);
    }

    router_kernel<<<N, 256>>>(x, rw, xh, N);
    assign_kernel<<<1, 256>>>(N);

    // GEMM1 (gather A from xh via slot->token): -> gelu -> act (fp16)
    gemm_h<true, true, __half><<<dim3(F / BN, NSLOT / BM), GTHREADS, GEMM_SMEM>>>(
        xh, w1h, b1, acth, F, H, stok, zrow);
    // GEMM2: act[4096,8192] @ w2h^T + b2 -> h (fp32)
    gemm_h<false, false, float><<<dim3(H / BN, NSLOT / BM), GTHREADS, GEMM_SMEM>>>(
        acth, w2h, b2, hbf, H, F, nullptr, nullptr);

    combine_kernel<<<N, 256>>>(N, out);
}